// round 7
// baseline (speedup 1.0000x reference)
#include <cuda_runtime.h>
#include <cstdint>

// ---------------------------------------------------------------------------
// edge_aggregation (B=4, E=8000, N=2000, D=256, HID=128, T=5)
// tf32 mma.sync.m16n8k8, cp.async 3-stage pipeline, ldmatrix fragment loads.
// B operands pre-transposed to n-major ([n][k]) so both A and B fragments load
// via one ldmatrix.x4 each (b16 ldsm == 8x4 b32 tile, lane L <- (L/4, L%4)).
//   edges = H @ ori                      GEMM1  M=8000 N=256 K=2000  x4
//   h     = relu(edges@W1[t]+b1)         MLP1   M=32000 N=128 K=256  x5
//   ef   += gate_t*(h@W2[t]+b2)          MLP2   M=32000 N=256 K=128  x5
//   out[:, :256] = H^T @ ef              GEMM3  M=2000 N=256 K=8000  (TRANS_A)
//   out[:, 256:] = ori
// ---------------------------------------------------------------------------

__device__ uint32_t g_Ht[4L * 8000 * 2000];    // 256 MB tf32
__device__ uint32_t g_oriT[4 * 256 * 2000];    // [b][d][n] tf32
__device__ uint32_t g_W1T[5 * 128 * 256];      // [t][h][d] tf32
__device__ uint32_t g_W2T[5 * 256 * 128];      // [t][d][h] tf32
__device__ uint32_t g_edges[32000 * 256];      // tf32 (GEMM1 out)
__device__ uint32_t g_ht[32000 * 128];         // tf32 (MLP1 out)
__device__ float    g_ef[32000 * 256];         // fp32 accumulator
__device__ uint32_t g_efT[4 * 256 * 8000];     // [b][d][e] tf32

// ---------------- PTX helpers ----------------
__device__ __forceinline__ uint32_t smem_u32(const void* p) {
    uint32_t a;
    asm("{ .reg .u64 t; cvta.to.shared.u64 t, %1; cvt.u32.u64 %0, t; }"
        : "=r"(a) : "l"(p));
    return a;
}
__device__ __forceinline__ void cpasync16(uint32_t dst, const void* src, uint32_t sz) {
    asm volatile("cp.async.cg.shared.global [%0], [%1], 16, %2;"
                 :: "r"(dst), "l"(src), "r"(sz) : "memory");
}
#define CP_COMMIT() asm volatile("cp.async.commit_group;" ::: "memory")
#define CP_WAIT1()  asm volatile("cp.async.wait_group 1;" ::: "memory")

__device__ __forceinline__ uint32_t lds32(uint32_t a) {
    uint32_t v;
    asm volatile("ld.shared.b32 %0, [%1];" : "=r"(v) : "r"(a));
    return v;
}
__device__ __forceinline__ void ldsm_x4(uint32_t (&r)[4], uint32_t a) {
    asm volatile("ldmatrix.sync.aligned.m8n8.x4.shared.b16 {%0,%1,%2,%3}, [%4];"
                 : "=r"(r[0]), "=r"(r[1]), "=r"(r[2]), "=r"(r[3]) : "r"(a));
}
__device__ __forceinline__ uint32_t f2tf32(float x) {
    uint32_t r;
    asm("cvt.rna.tf32.f32 %0, %1;" : "=r"(r) : "f"(x));
    return r;
}
__device__ __forceinline__ void mma_tf32(float (&c)[4], const uint32_t (&a)[4],
                                         uint32_t b0, uint32_t b1) {
    asm volatile(
        "mma.sync.aligned.m16n8k8.row.col.f32.tf32.tf32.f32 "
        "{%0,%1,%2,%3}, {%4,%5,%6,%7}, {%8,%9}, {%0,%1,%2,%3};"
        : "+f"(c[0]), "+f"(c[1]), "+f"(c[2]), "+f"(c[3])
        : "r"(a[0]), "r"(a[1]), "r"(a[2]), "r"(a[3]), "r"(b0), "r"(b1));
}

// ---------------------------------------------------------------------------
// Tile 128 x BN (BN = 128 or 256), K-chunk 32, 512 threads (16 warps, 4Mx4N).
// Smem per stage: A non-trans [128 m][36 w] = 18432 B; A trans [32 k][136 w]
// = 17408 B; B n-major [BN n][36 w] = BN*144 B. 3-stage cp.async pipeline.
// Fragments: A (non-trans) and B via ldmatrix.x4; A (trans) via lds32.
// EPI 0: C=acc | 1: relu(acc+bias) | 2: C (init? = : +=) gate*(acc+bias)
// Requires N == BN*gridDim.y, K % 4 == 0, M % 4 == 0, niter >= 2.
// ---------------------------------------------------------------------------
template <int EPI, bool TRANS_A, int BN, bool OUT_TF32>
__global__ __launch_bounds__(512, 1)
void gemm_tf32(const uint32_t* __restrict__ A, const uint32_t* __restrict__ BT,
               void* __restrict__ Cv, int M, int N, int K,
               long sA, long sB, long sC, int lda, int ldb, int ldc,
               const float* __restrict__ bias, const float* __restrict__ gate,
               int gidx, int gld, int init_flag)
{
    constexpr int AS_BYTES = TRANS_A ? 32 * 544 : 128 * 144;
    constexpr int BS_BYTES = BN * 144;
    constexpr int WTN = BN / 4;        // warp tile N (64 or 32)
    constexpr int NT  = WTN / 8;       // 8-wide n frags per warp (8 or 4)
    constexpr int NP  = NT / 2;        // ldsm pairs (4 or 2)
    constexpr int BCH = BN / 64;       // B cp.async chunks per thread (4 or 2)

    extern __shared__ __align__(16) char dyn[];
    const uint32_t as0 = smem_u32(dyn);
    const uint32_t bs0 = as0 + 3 * AS_BYTES;

    const int tid = threadIdx.x;
    const int warp = tid >> 5, lane = tid & 31;
    const int wm = warp & 3, wn = warp >> 2;
    const int m_w = wm * 32, n_w = wn * WTN;
    const int g = lane >> 2, t = lane & 3;

    const int z = blockIdx.z;
    A += (long)z * sA;  BT += (long)z * sB;
    const long m0 = (long)blockIdx.x * 128;
    const int  n0 = blockIdx.y * BN;

    const int niter = (K + 31) / 32;

    float acc[2][NT][4];
#pragma unroll
    for (int a = 0; a < 2; a++)
#pragma unroll
        for (int b = 0; b < NT; b++)
#pragma unroll
            for (int c = 0; c < 4; c++) acc[a][b][c] = 0.f;

    auto issue = [&](int it, int stage) {
        const long k0 = (long)it * 32;
        if constexpr (!TRANS_A) {
#pragma unroll
            for (int p = 0; p < 2; p++) {
                const int ch = tid + p * 512;
                const int row = ch >> 3, c = ch & 7;
                const long gm = m0 + row, gk = k0 + c * 4;
                const uint32_t ok = (gm < M && gk < K);
                const uint32_t* src = A + (ok ? gm * (long)lda + gk : 0);
                cpasync16(as0 + stage * AS_BYTES + row * 144 + c * 16,
                          src, ok ? 16u : 0u);
            }
        } else {
#pragma unroll
            for (int p = 0; p < 2; p++) {
                const int ch = tid + p * 512;
                const int kr = ch >> 5, m4 = ch & 31;
                const long gk = k0 + kr, gm = m0 + m4 * 4;
                const uint32_t ok = (gk < K && gm < M);
                const uint32_t* src = A + (ok ? gk * (long)lda + gm : 0);
                cpasync16(as0 + stage * AS_BYTES + kr * 544 + m4 * 16,
                          src, ok ? 16u : 0u);
            }
        }
        // B: [BN n][32 k] from BT [n][Ktot]
#pragma unroll
        for (int p = 0; p < BCH; p++) {
            const int ch = tid + p * 512;
            const int r = ch >> 3, c = ch & 7;
            const long gk = k0 + c * 4;
            const uint32_t ok = (gk < K);
            const uint32_t* src = BT + (ok ? (long)(n0 + r) * ldb + gk : 0);
            cpasync16(bs0 + stage * BS_BYTES + r * 144 + c * 16,
                      src, ok ? 16u : 0u);
        }
        CP_COMMIT();
    };

    auto compute = [&](int stage) {
        const uint32_t as = as0 + stage * AS_BYTES;
        const uint32_t bs = bs0 + stage * BS_BYTES;
#pragma unroll
        for (int ks = 0; ks < 32; ks += 8) {
            uint32_t a[2][4], b[NT][2];
            if constexpr (!TRANS_A) {
                // ldsm: lanes 0-7 -> (m 0-7, k ks..+3); 8-15 -> m+8; 16-23 ->
                // (m 0-7, k+4); 24-31 -> (m+8, k+4)
#pragma unroll
                for (int mt = 0; mt < 2; mt++) {
                    const uint32_t addr = as +
                        (m_w + mt * 16 + (lane & 15)) * 144 +
                        ks * 4 + ((lane >> 4) << 4);
                    ldsm_x4(a[mt], addr);
                }
            } else {
                const uint32_t base = as + (ks + t) * 544 + (m_w + g) * 4;
#pragma unroll
                for (int mt = 0; mt < 2; mt++) {
                    const uint32_t ab = base + mt * 64;
                    a[mt][0] = lds32(ab);
                    a[mt][1] = lds32(ab + 32);
                    a[mt][2] = lds32(ab + 4 * 544);
                    a[mt][3] = lds32(ab + 4 * 544 + 32);
                }
            }
            // B ldsm: mat0 (n 0-7, k), mat1 (n 0-7, k+4), mat2 (n 8-15, k),
            // mat3 (n 8-15, k+4)
#pragma unroll
            for (int np = 0; np < NP; np++) {
                uint32_t r4[4];
                const uint32_t addr = bs +
                    (n_w + np * 16 + ((lane >> 4) << 3) + (lane & 7)) * 144 +
                    ks * 4 + (((lane >> 3) & 1) << 4);
                ldsm_x4(r4, addr);
                b[np * 2][0] = r4[0];
                b[np * 2][1] = r4[1];
                b[np * 2 + 1][0] = r4[2];
                b[np * 2 + 1][1] = r4[3];
            }
#pragma unroll
            for (int mt = 0; mt < 2; mt++)
#pragma unroll
                for (int nt = 0; nt < NT; nt++)
                    mma_tf32(acc[mt][nt], a[mt], b[nt][0], b[nt][1]);
        }
    };

    // prologue (all uses have niter >= 2)
    issue(0, 0);
    issue(1, 1);

    for (int it = 0; it < niter; it++) {
        CP_WAIT1();
        __syncthreads();
        if (it + 2 < niter) issue(it + 2, (it + 2) % 3);
        compute(it % 3);
    }

    // ---------------- epilogue ----------------
    const int tg = t * 2;
#pragma unroll
    for (int mt = 0; mt < 2; mt++) {
#pragma unroll
        for (int h = 0; h < 2; h++) {
            const long r = m0 + m_w + mt * 16 + g + h * 8;
            if (r >= M) continue;
            float gt = 0.f;
            if (EPI == 2) gt = gate[r * (long)gld + gidx];
#pragma unroll
            for (int nt = 0; nt < NT; nt++) {
                const int col = n_w + nt * 8 + tg;   // within [0, BN)
                float v0 = acc[mt][nt][h * 2 + 0];
                float v1 = acc[mt][nt][h * 2 + 1];
                if (EPI == 1) {
                    float2 bb = *(const float2*)(bias + n0 + col);
                    v0 = fmaxf(v0 + bb.x, 0.f);
                    v1 = fmaxf(v1 + bb.y, 0.f);
                } else if (EPI == 2) {
                    float2 bb = *(const float2*)(bias + n0 + col);
                    v0 = gt * (v0 + bb.x);
                    v1 = gt * (v1 + bb.y);
                }
                if constexpr (OUT_TF32) {
                    uint32_t* p = (uint32_t*)Cv + z * sC + r * (long)ldc + n0 + col;
                    uint2 o;
                    o.x = f2tf32(v0);
                    o.y = f2tf32(v1);
                    *reinterpret_cast<uint2*>(p) = o;
                } else {
                    float* p = (float*)Cv + z * sC + r * (long)ldc + n0 + col;
                    if (EPI == 2 && !init_flag) {
                        float2 o = *(const float2*)p;
                        v0 += o.x; v1 += o.y;
                    }
                    *reinterpret_cast<float2*>(p) = make_float2(v0, v1);
                }
            }
        }
    }
}

// ---------------------------------------------------------------------------
__global__ void f32_to_tf32_kernel(const float* __restrict__ src,
                                   uint32_t* __restrict__ dst, long n4)
{
    const long i = (long)blockIdx.x * blockDim.x + threadIdx.x;
    if (i >= n4) return;
    float4 v = ((const float4*)src)[i];
    uint4 o;
    o.x = f2tf32(v.x);
    o.y = f2tf32(v.y);
    o.z = f2tf32(v.z);
    o.w = f2tf32(v.w);
    ((uint4*)dst)[i] = o;
}

// in fp32 [z][R][C] -> out tf32 [z][C][R]   (C % 32 == 0; R guarded)
__global__ void trans_cvt_kernel(const float* __restrict__ src,
                                 uint32_t* __restrict__ dst,
                                 int R, int C, long sIn, long sOut)
{
    __shared__ float tbuf[32][33];
    const int r0 = blockIdx.x * 32, c0 = blockIdx.y * 32, z = blockIdx.z;
    const int tx = threadIdx.x, ty = threadIdx.y;
    const float* in = src + (long)z * sIn;
#pragma unroll
    for (int i = ty; i < 32; i += 8) {
        const int r = r0 + i;
        tbuf[i][tx] = (r < R) ? in[(long)r * C + c0 + tx] : 0.f;
    }
    __syncthreads();
    uint32_t* outp = dst + (long)z * sOut;
#pragma unroll
    for (int i = ty; i < 32; i += 8) {
        const int r = r0 + tx;
        if (r < R) outp[(long)(c0 + i) * R + r] = f2tf32(tbuf[tx][i]);
    }
}

// out[b,n,256:512] = ori[b,n,:]
__global__ void concat_ori_kernel(const float* __restrict__ ori,
                                  float* __restrict__ out, int total4)
{
    int idx = blockIdx.x * blockDim.x + threadIdx.x;
    if (idx >= total4) return;
    int d4 = idx & 63;
    int bn = idx >> 6;
    float4 v = ((const float4*)ori)[idx];
    ((float4*)(out + (long)bn * 512 + 256))[d4] = v;
}

// ---------------------------------------------------------------------------
extern "C" void kernel_launch(void* const* d_in, const int* in_sizes, int n_in,
                              void* d_out, int out_size)
{
    const float* ed  = (const float*)d_in[0];   // [4,8000,5]
    const float* H   = (const float*)d_in[1];   // [4,8000,2000]
    const float* ori = (const float*)d_in[2];   // [4,2000,256]
    const float* W1  = (const float*)d_in[3];   // [5,256,128]
    const float* b1  = (const float*)d_in[4];   // [5,128]
    const float* W2  = (const float*)d_in[5];   // [5,128,256]
    const float* b2  = (const float*)d_in[6];   // [5,256]
    float* out = (float*)d_out;                 // [4,2000,512]

    uint32_t *Ht, *oriT, *W1T, *W2T, *edges, *ht, *efT;
    float* ef;
    cudaGetSymbolAddress((void**)&Ht, g_Ht);
    cudaGetSymbolAddress((void**)&oriT, g_oriT);
    cudaGetSymbolAddress((void**)&W1T, g_W1T);
    cudaGetSymbolAddress((void**)&W2T, g_W2T);
    cudaGetSymbolAddress((void**)&edges, g_edges);
    cudaGetSymbolAddress((void**)&ht, g_ht);
    cudaGetSymbolAddress((void**)&ef, g_ef);
    cudaGetSymbolAddress((void**)&efT, g_efT);

    const int SM_G1  = 3 * (128 * 144) + 3 * (256 * 144);   // 165888
    const int SM_M1  = 3 * (128 * 144) + 3 * (128 * 144);   // 110592
    const int SM_M2  = 3 * (128 * 144) + 3 * (256 * 144);   // 165888
    const int SM_G3  = 3 * (32 * 544)  + 3 * (256 * 144);   // 162816
    cudaFuncSetAttribute(gemm_tf32<0, false, 256, true>,
                         cudaFuncAttributeMaxDynamicSharedMemorySize, SM_G1);
    cudaFuncSetAttribute(gemm_tf32<1, false, 128, true>,
                         cudaFuncAttributeMaxDynamicSharedMemorySize, SM_M1);
    cudaFuncSetAttribute(gemm_tf32<2, false, 256, false>,
                         cudaFuncAttributeMaxDynamicSharedMemorySize, SM_M2);
    cudaFuncSetAttribute(gemm_tf32<0, true, 256, false>,
                         cudaFuncAttributeMaxDynamicSharedMemorySize, SM_G3);

    // 0a) H -> tf32 (elementwise)
    {
        const long n4 = 4L * 8000 * 2000 / 4;
        f32_to_tf32_kernel<<<(unsigned)((n4 + 255) / 256), 256>>>(H, Ht, n4);
    }
    // 0b) transpose+convert the B operands to n-major tf32
    trans_cvt_kernel<<<dim3(63, 8, 4), dim3(32, 8)>>>(
        ori, oriT, 2000, 256, 2000L * 256, 2000L * 256);
    trans_cvt_kernel<<<dim3(8, 4, 5), dim3(32, 8)>>>(
        W1, W1T, 256, 128, 256L * 128, 256L * 128);
    trans_cvt_kernel<<<dim3(4, 8, 5), dim3(32, 8)>>>(
        W2, W2T, 128, 256, 128L * 256, 128L * 256);

    // 1) edges = H @ ori   (A=Ht, B=oriT n-major, tf32 out)
    gemm_tf32<0, false, 256, true><<<dim3(63, 1, 4), 512, SM_G1>>>(
        Ht, oriT, edges, 8000, 256, 2000,
        8000L * 2000, 256L * 2000, 8000L * 256,
        2000, 2000, 256, nullptr, nullptr, 0, 0, 0);

    // 2) per-type MLP (M = 32000 folded)
    for (int t = 0; t < 5; t++) {
        gemm_tf32<1, false, 128, true><<<dim3(250, 1, 1), 512, SM_M1>>>(
            edges, W1T + (long)t * 128 * 256, ht, 32000, 128, 256,
            0, 0, 0, 256, 256, 128, b1 + t * 128, nullptr, 0, 0, 0);
        gemm_tf32<2, false, 256, false><<<dim3(250, 1, 1), 512, SM_M2>>>(
            ht, W2T + (long)t * 256 * 128, ef, 32000, 256, 128,
            0, 0, 0, 128, 128, 256, b2 + t * 256, ed, t, 5, (t == 0) ? 1 : 0);
    }

    // 3) efT = transpose+convert(ef) per batch: [8000,256] -> [256,8000]
    trans_cvt_kernel<<<dim3(250, 8, 4), dim3(32, 8)>>>(
        ef, efT, 8000, 256, 8000L * 256, 8000L * 256);

    // 4) out[:, :, :256] = H^T @ ef   (A=Ht TRANS_A, B=efT n-major)
    gemm_tf32<0, true, 256, false><<<dim3(16, 1, 4), 512, SM_G3>>>(
        Ht, efT, out, 2000, 256, 8000,
        8000L * 2000, 256L * 8000, 2000L * 512,
        2000, 8000, 512, nullptr, nullptr, 0, 0, 0);

    // 5) out[:, :, 256:] = ori
    concat_ori_kernel<<<(4 * 2000 * 64 + 255) / 256, 256>>>(ori, out, 4 * 2000 * 64);
}

// round 8
// speedup vs baseline: 1.1477x; 1.1477x over previous
#include <cuda_runtime.h>
#include <cstdint>

// ---------------------------------------------------------------------------
// edge_aggregation (B=4, E=8000, N=2000, D=256, HID=128, T=5)
// tf32 mma.sync.m16n8k8 + cp.async 3-stage pipeline + ldmatrix fragments.
// H consumed as raw fp32 with cvt.rna.tf32 applied post-fragment-load
// (no 256MB pre-convert). B operands pre-transposed to n-major tf32.
// GEMM3 split-K x4 with fp32 partials + reduce.
//   edges = H @ ori                      GEMM1  M=8000 N=256 K=2000  x4
//   h     = relu(edges@W1[t]+b1)         MLP1   M=32000 N=128 K=256  x5 (one launch)
//   ef   += gate_t*(h@W2[t]+b2)          MLP2   M=32000 N=256 K=128  x5
//   out[:, :256] = H^T @ ef              GEMM3  M=2000 N=256 K=8000  split-K x4
//   out[:, 256:] = ori
// ---------------------------------------------------------------------------

__device__ uint32_t g_oriT[4 * 256 * 2000];     // [b][d][n] tf32
__device__ uint32_t g_W1T[5 * 128 * 256];       // [t][h][d] tf32
__device__ uint32_t g_W2T[5 * 256 * 128];       // [t][d][h] tf32
__device__ uint32_t g_edges[32000 * 256];       // tf32 (GEMM1 out)
__device__ uint32_t g_ht5[5L * 32000 * 128];    // tf32 (MLP1 out, per type)
__device__ float    g_ef[32000 * 256];          // fp32 accumulator
__device__ uint32_t g_efT[4 * 256 * 8000];      // [b][d][e] tf32
__device__ float    g_part[4L * 4 * 2000 * 256]; // split-K partials

// ---------------- PTX helpers ----------------
__device__ __forceinline__ uint32_t smem_u32(const void* p) {
    uint32_t a;
    asm("{ .reg .u64 t; cvta.to.shared.u64 t, %1; cvt.u32.u64 %0, t; }"
        : "=r"(a) : "l"(p));
    return a;
}
__device__ __forceinline__ void cpasync16(uint32_t dst, const void* src, uint32_t sz) {
    asm volatile("cp.async.cg.shared.global [%0], [%1], 16, %2;"
                 :: "r"(dst), "l"(src), "r"(sz) : "memory");
}
#define CP_COMMIT() asm volatile("cp.async.commit_group;" ::: "memory")
#define CP_WAIT1()  asm volatile("cp.async.wait_group 1;" ::: "memory")

__device__ __forceinline__ uint32_t lds32(uint32_t a) {
    uint32_t v;
    asm volatile("ld.shared.b32 %0, [%1];" : "=r"(v) : "r"(a));
    return v;
}
__device__ __forceinline__ void ldsm_x4(uint32_t (&r)[4], uint32_t a) {
    asm volatile("ldmatrix.sync.aligned.m8n8.x4.shared.b16 {%0,%1,%2,%3}, [%4];"
                 : "=r"(r[0]), "=r"(r[1]), "=r"(r[2]), "=r"(r[3]) : "r"(a));
}
__device__ __forceinline__ uint32_t f2tf32(float x) {
    uint32_t r;
    asm("cvt.rna.tf32.f32 %0, %1;" : "=r"(r) : "f"(x));
    return r;
}
__device__ __forceinline__ void mma_tf32(float (&c)[4], const uint32_t (&a)[4],
                                         uint32_t b0, uint32_t b1) {
    asm volatile(
        "mma.sync.aligned.m16n8k8.row.col.f32.tf32.tf32.f32 "
        "{%0,%1,%2,%3}, {%4,%5,%6,%7}, {%8,%9}, {%0,%1,%2,%3};"
        : "+f"(c[0]), "+f"(c[1]), "+f"(c[2]), "+f"(c[3])
        : "r"(a[0]), "r"(a[1]), "r"(a[2]), "r"(a[3]), "r"(b0), "r"(b1));
}

// ---------------------------------------------------------------------------
// Tile 128x128, K-chunk 32, 512 threads (16 warps: 4M x 4N, 32x32 per warp).
// Smem/stage: A non-trans [128][36w]=18432B; A trans [32][136w]=17408B;
//             B n-major [128][36w]=18432B. 3-stage cp.async.
// A_CVT: A gmem is raw fp32; cvt.rna.tf32 applied after fragment load.
// z decomposition: zb = blockIdx.z % nz (batch), sp = blockIdx.z / nz (splitK).
// EPI 0: C=acc | 1: relu(acc+bias) | 2: C (init? = : +=) gate*(acc+bias)
// Requires N==128*gridDim.y, M%4==0, K%4==0, niter>=2.
// ---------------------------------------------------------------------------
template <int EPI, bool TRANS_A, bool A_CVT, bool OUT_TF32>
__global__ __launch_bounds__(512, 1)
void gemm_tf32(const uint32_t* __restrict__ A, const uint32_t* __restrict__ BT,
               void* __restrict__ Cv, int M, int N, int K,
               long sA, long sB, long sC,
               long aSplit, long bSplit, long cSplit, int nz,
               int lda, int ldb, int ldc,
               const float* __restrict__ bias, long biasZ,
               const float* __restrict__ gate,
               int gidx, int gld, int init_flag)
{
    constexpr int AS_BYTES = TRANS_A ? 32 * 544 : 128 * 144;
    constexpr int BS_BYTES = 128 * 144;

    extern __shared__ __align__(16) char dyn[];
    const uint32_t as0 = smem_u32(dyn);
    const uint32_t bs0 = as0 + 3 * AS_BYTES;

    const int tid = threadIdx.x;
    const int warp = tid >> 5, lane = tid & 31;
    const int wm = warp & 3, wn = warp >> 2;
    const int m_w = wm * 32, n_w = wn * 32;
    const int g = lane >> 2, t = lane & 3;

    const int zb = blockIdx.z % nz;
    const int sp = blockIdx.z / nz;
    A  += zb * sA + sp * aSplit;
    BT += zb * sB + sp * bSplit;
    bias += zb * biasZ;
    const long cbase = zb * sC + sp * cSplit;

    const long m0 = (long)blockIdx.x * 128;
    const int  n0 = blockIdx.y * 128;

    const int niter = (K + 31) / 32;

    float acc[2][4][4];
#pragma unroll
    for (int a = 0; a < 2; a++)
#pragma unroll
        for (int b = 0; b < 4; b++)
#pragma unroll
            for (int c = 0; c < 4; c++) acc[a][b][c] = 0.f;

    auto issue = [&](int it, int stage) {
        const long k0 = (long)it * 32;
        if constexpr (!TRANS_A) {
#pragma unroll
            for (int p = 0; p < 2; p++) {
                const int ch = tid + p * 512;
                const int row = ch >> 3, c = ch & 7;
                const long gm = m0 + row, gk = k0 + c * 4;
                const uint32_t ok = (gm < M && gk < K);
                const uint32_t* src = A + (ok ? gm * (long)lda + gk : 0);
                cpasync16(as0 + stage * AS_BYTES + row * 144 + c * 16,
                          src, ok ? 16u : 0u);
            }
        } else {
#pragma unroll
            for (int p = 0; p < 2; p++) {
                const int ch = tid + p * 512;
                const int kr = ch >> 5, m4 = ch & 31;
                const long gk = k0 + kr, gm = m0 + m4 * 4;
                const uint32_t ok = (gk < K && gm < M);
                const uint32_t* src = A + (ok ? gk * (long)lda + gm : 0);
                cpasync16(as0 + stage * AS_BYTES + kr * 544 + m4 * 16,
                          src, ok ? 16u : 0u);
            }
        }
        // B: [128 n][32 k] from BT [n][Ktot]
#pragma unroll
        for (int p = 0; p < 2; p++) {
            const int ch = tid + p * 512;
            const int r = ch >> 3, c = ch & 7;
            const long gk = k0 + c * 4;
            const uint32_t ok = (gk < K);
            const uint32_t* src = BT + (ok ? (long)(n0 + r) * ldb + gk : 0);
            cpasync16(bs0 + stage * BS_BYTES + r * 144 + c * 16,
                      src, ok ? 16u : 0u);
        }
        CP_COMMIT();
    };

    auto compute = [&](int stage) {
        const uint32_t as = as0 + stage * AS_BYTES;
        const uint32_t bs = bs0 + stage * BS_BYTES;
#pragma unroll
        for (int ks = 0; ks < 32; ks += 8) {
            uint32_t a[2][4], b[4][2];
            if constexpr (!TRANS_A) {
#pragma unroll
                for (int mt = 0; mt < 2; mt++) {
                    const uint32_t addr = as +
                        (m_w + mt * 16 + (lane & 15)) * 144 +
                        ks * 4 + ((lane >> 4) << 4);
                    ldsm_x4(a[mt], addr);
                }
            } else {
                const uint32_t base = as + (ks + t) * 544 + (m_w + g) * 4;
#pragma unroll
                for (int mt = 0; mt < 2; mt++) {
                    const uint32_t ab = base + mt * 64;
                    a[mt][0] = lds32(ab);
                    a[mt][1] = lds32(ab + 32);
                    a[mt][2] = lds32(ab + 4 * 544);
                    a[mt][3] = lds32(ab + 4 * 544 + 32);
                }
            }
            if constexpr (A_CVT) {
#pragma unroll
                for (int mt = 0; mt < 2; mt++)
#pragma unroll
                    for (int q = 0; q < 4; q++)
                        a[mt][q] = f2tf32(__uint_as_float(a[mt][q]));
            }
            // B ldsm pairs: mats (n0-7,k),(n0-7,k+4),(n8-15,k),(n8-15,k+4)
#pragma unroll
            for (int np = 0; np < 2; np++) {
                uint32_t r4[4];
                const uint32_t addr = bs +
                    (n_w + np * 16 + ((lane >> 4) << 3) + (lane & 7)) * 144 +
                    ks * 4 + (((lane >> 3) & 1) << 4);
                ldsm_x4(r4, addr);
                b[np * 2][0] = r4[0];
                b[np * 2][1] = r4[1];
                b[np * 2 + 1][0] = r4[2];
                b[np * 2 + 1][1] = r4[3];
            }
#pragma unroll
            for (int mt = 0; mt < 2; mt++)
#pragma unroll
                for (int nt = 0; nt < 4; nt++)
                    mma_tf32(acc[mt][nt], a[mt], b[nt][0], b[nt][1]);
        }
    };

    issue(0, 0);
    issue(1, 1);

    for (int it = 0; it < niter; it++) {
        CP_WAIT1();
        __syncthreads();
        if (it + 2 < niter) issue(it + 2, (it + 2) % 3);
        compute(it % 3);
    }

    // ---------------- epilogue ----------------
    const int tg = t * 2;
#pragma unroll
    for (int mt = 0; mt < 2; mt++) {
#pragma unroll
        for (int h = 0; h < 2; h++) {
            const long r = m0 + m_w + mt * 16 + g + h * 8;
            if (r >= M) continue;
            float gt = 0.f;
            if (EPI == 2) gt = gate[r * (long)gld + gidx];
#pragma unroll
            for (int nt = 0; nt < 4; nt++) {
                const int col = n_w + nt * 8 + tg;
                float v0 = acc[mt][nt][h * 2 + 0];
                float v1 = acc[mt][nt][h * 2 + 1];
                if (EPI == 1) {
                    float2 bb = *(const float2*)(bias + n0 + col);
                    v0 = fmaxf(v0 + bb.x, 0.f);
                    v1 = fmaxf(v1 + bb.y, 0.f);
                } else if (EPI == 2) {
                    float2 bb = *(const float2*)(bias + n0 + col);
                    v0 = gt * (v0 + bb.x);
                    v1 = gt * (v1 + bb.y);
                }
                if constexpr (OUT_TF32) {
                    uint32_t* p = (uint32_t*)Cv + cbase + r * (long)ldc + n0 + col;
                    uint2 o;
                    o.x = f2tf32(v0);
                    o.y = f2tf32(v1);
                    *reinterpret_cast<uint2*>(p) = o;
                } else {
                    float* p = (float*)Cv + cbase + r * (long)ldc + n0 + col;
                    if (EPI == 2 && !init_flag) {
                        float2 o = *(const float2*)p;
                        v0 += o.x; v1 += o.y;
                    }
                    *reinterpret_cast<float2*>(p) = make_float2(v0, v1);
                }
            }
        }
    }
}

// ---------------------------------------------------------------------------
// in fp32 [z][R][C] -> out tf32 [z][C][R]   (C % 32 == 0; R guarded)
__global__ void trans_cvt_kernel(const float* __restrict__ src,
                                 uint32_t* __restrict__ dst,
                                 int R, int C, long sIn, long sOut)
{
    __shared__ float tbuf[32][33];
    const int r0 = blockIdx.x * 32, c0 = blockIdx.y * 32, z = blockIdx.z;
    const int tx = threadIdx.x, ty = threadIdx.y;
    const float* in = src + (long)z * sIn;
#pragma unroll
    for (int i = ty; i < 32; i += 8) {
        const int r = r0 + i;
        tbuf[i][tx] = (r < R) ? in[(long)r * C + c0 + tx] : 0.f;
    }
    __syncthreads();
    uint32_t* outp = dst + (long)z * sOut;
#pragma unroll
    for (int i = ty; i < 32; i += 8) {
        const int r = r0 + tx;
        if (r < R) outp[(long)(c0 + i) * R + r] = f2tf32(tbuf[tx][i]);
    }
}

// out[b,n,0:256] = sum_s part[s][b][n][:]
__global__ void reduce_part_kernel(const float* __restrict__ part,
                                   float* __restrict__ out, int total4)
{
    const int idx = blockIdx.x * blockDim.x + threadIdx.x;
    if (idx >= total4) return;
    const int d4 = idx & 63;
    const int bn = idx >> 6;
    const long stride4 = 4L * 2000 * 64;
    float4 s = ((const float4*)part)[idx];
#pragma unroll
    for (int sp = 1; sp < 4; sp++) {
        float4 v = ((const float4*)part)[idx + sp * stride4];
        s.x += v.x; s.y += v.y; s.z += v.z; s.w += v.w;
    }
    ((float4*)out)[(long)bn * 128 + d4] = s;
}

// out[b,n,256:512] = ori[b,n,:]
__global__ void concat_ori_kernel(const float* __restrict__ ori,
                                  float* __restrict__ out, int total4)
{
    int idx = blockIdx.x * blockDim.x + threadIdx.x;
    if (idx >= total4) return;
    int d4 = idx & 63;
    int bn = idx >> 6;
    float4 v = ((const float4*)ori)[idx];
    ((float4*)out)[(long)bn * 128 + 64 + d4] = v;
}

// ---------------------------------------------------------------------------
extern "C" void kernel_launch(void* const* d_in, const int* in_sizes, int n_in,
                              void* d_out, int out_size)
{
    const float* ed  = (const float*)d_in[0];   // [4,8000,5]
    const float* H   = (const float*)d_in[1];   // [4,8000,2000]
    const float* ori = (const float*)d_in[2];   // [4,2000,256]
    const float* W1  = (const float*)d_in[3];   // [5,256,128]
    const float* b1  = (const float*)d_in[4];   // [5,128]
    const float* W2  = (const float*)d_in[5];   // [5,128,256]
    const float* b2  = (const float*)d_in[6];   // [5,256]
    float* out = (float*)d_out;                 // [4,2000,512]

    uint32_t *oriT, *W1T, *W2T, *edges, *ht5, *efT;
    float *ef, *part;
    cudaGetSymbolAddress((void**)&oriT, g_oriT);
    cudaGetSymbolAddress((void**)&W1T, g_W1T);
    cudaGetSymbolAddress((void**)&W2T, g_W2T);
    cudaGetSymbolAddress((void**)&edges, g_edges);
    cudaGetSymbolAddress((void**)&ht5, g_ht5);
    cudaGetSymbolAddress((void**)&ef, g_ef);
    cudaGetSymbolAddress((void**)&efT, g_efT);
    cudaGetSymbolAddress((void**)&part, g_part);

    const int SM_NT = 3 * (128 * 144 + 128 * 144);   // 110592
    const int SM_T  = 3 * (32 * 544 + 128 * 144);    // 107520
    cudaFuncSetAttribute(gemm_tf32<0, false, true, true>,
                         cudaFuncAttributeMaxDynamicSharedMemorySize, SM_NT);
    cudaFuncSetAttribute(gemm_tf32<1, false, false, true>,
                         cudaFuncAttributeMaxDynamicSharedMemorySize, SM_NT);
    cudaFuncSetAttribute(gemm_tf32<2, false, false, false>,
                         cudaFuncAttributeMaxDynamicSharedMemorySize, SM_NT);
    cudaFuncSetAttribute(gemm_tf32<0, true, true, false>,
                         cudaFuncAttributeMaxDynamicSharedMemorySize, SM_T);

    // 0) transpose+convert B operands to n-major tf32
    trans_cvt_kernel<<<dim3(63, 8, 4), dim3(32, 8)>>>(
        ori, oriT, 2000, 256, 2000L * 256, 2000L * 256);
    trans_cvt_kernel<<<dim3(8, 4, 5), dim3(32, 8)>>>(
        W1, W1T, 256, 128, 256L * 128, 256L * 128);
    trans_cvt_kernel<<<dim3(4, 8, 5), dim3(32, 8)>>>(
        W2, W2T, 128, 256, 128L * 256, 128L * 256);

    // 1) edges = H @ ori   (A = H fp32 + in-loop cvt; B = oriT; tf32 out)
    gemm_tf32<0, false, true, true><<<dim3(63, 2, 4), 512, SM_NT>>>(
        (const uint32_t*)H, oriT, edges, 8000, 256, 2000,
        8000L * 2000, 256L * 2000, 8000L * 256, 0, 0, 0, 4,
        2000, 2000, 256, nullptr, 0, nullptr, 0, 0, 0);

    // 2a) MLP1 for all 5 types in one launch (z = t)
    gemm_tf32<1, false, false, true><<<dim3(250, 1, 5), 512, SM_NT>>>(
        edges, W1T, ht5, 32000, 128, 256,
        0, 128L * 256, 32000L * 128, 0, 0, 0, 5,
        256, 256, 128, b1, 128, nullptr, 0, 0, 0);

    // 2b) MLP2 per type (sequential: ef accumulation)
    for (int t = 0; t < 5; t++) {
        gemm_tf32<2, false, false, false><<<dim3(250, 2, 1), 512, SM_NT>>>(
            ht5 + (long)t * 32000 * 128, W2T + (long)t * 256 * 128, ef,
            32000, 256, 128,
            0, 0, 0, 0, 0, 0, 1,
            128, 128, 256, b2 + t * 256, 0, ed, t, 5, (t == 0) ? 1 : 0);
    }

    // 3) efT = transpose+convert(ef) per batch: [8000,256] -> [256,8000]
    trans_cvt_kernel<<<dim3(250, 8, 4), dim3(32, 8)>>>(
        ef, efT, 8000, 256, 8000L * 256, 8000L * 256);

    // 4) part[s] = H[ks]^T @ ef[ks]  (split-K x4; A = H fp32 TRANS + cvt)
    gemm_tf32<0, true, true, false><<<dim3(16, 2, 16), 512, SM_T>>>(
        (const uint32_t*)H, efT, part, 2000, 256, 2000,
        8000L * 2000, 256L * 8000, 2000L * 256,
        2000L * 2000, 2000, 4L * 2000 * 256, 4,
        2000, 8000, 256, nullptr, 0, nullptr, 0, 0, 0);

    // 5) out[:, :, :256] = sum_s part[s] ; out[:, :, 256:] = ori
    reduce_part_kernel<<<(4 * 2000 * 64 + 255) / 256, 256>>>(
        part, out, 4 * 2000 * 64);
    concat_ori_kernel<<<(4 * 2000 * 64 + 255) / 256, 256>>>(
        ori, out, 4 * 2000 * 64);
}

// round 11
// speedup vs baseline: 1.2560x; 1.0943x over previous
#include <cuda_runtime.h>
#include <cstdint>

// ---------------------------------------------------------------------------
// edge_aggregation (B=4, E=8000, N=2000, D=256, HID=128, T=5)
// tf32 mma.sync.m16n8k8 + cp.async 3-stage pipeline + ldmatrix fragments.
// Round 11: round-10 geometry (256-thread CTAs, 64x128 tiles, 2 CTAs/SM)
// + TAIL-RACE FIX: empty cp.async.commit_group in tail iterations so
// wait_group 1 always guarantees the chunk being computed is complete.
//   edges = H @ ori                      GEMM1  M=8000 N=256 K=2000  x4
//   h     = relu(edges@W1[t]+b1)         MLP1   M=32000 N=128 K=256  x5 (one launch)
//   ef   += gate_t*(h@W2[t]+b2)          MLP2   M=32000 N=256 K=128  x5
//   out[:, :256] = H^T @ ef              GEMM3  M=2000 N=256 K=8000  split-K x4
//   out[:, 256:] = ori
// ---------------------------------------------------------------------------

__device__ uint32_t g_oriT[4 * 256 * 2000];      // [b][d][n] tf32
__device__ uint32_t g_W1T[5 * 128 * 256];        // [t][h][d] tf32
__device__ uint32_t g_W2T[5 * 256 * 128];        // [t][d][h] tf32
__device__ uint32_t g_edges[32000 * 256];        // tf32 (GEMM1 out)
__device__ uint32_t g_ht5[5L * 32000 * 128];     // tf32 (MLP1 out, per type)
__device__ float    g_ef[32000 * 256];           // fp32 accumulator
__device__ uint32_t g_efT[4 * 256 * 8000];       // [b][d][e] tf32
__device__ float    g_part[4L * 4 * 2000 * 256]; // split-K partials

// ---------------- PTX helpers ----------------
__device__ __forceinline__ uint32_t smem_u32(const void* p) {
    uint32_t a;
    asm("{ .reg .u64 t; cvta.to.shared.u64 t, %1; cvt.u32.u64 %0, t; }"
        : "=r"(a) : "l"(p));
    return a;
}
__device__ __forceinline__ void cpasync16(uint32_t dst, const void* src, uint32_t sz) {
    asm volatile("cp.async.cg.shared.global [%0], [%1], 16, %2;"
                 :: "r"(dst), "l"(src), "r"(sz) : "memory");
}
#define CP_COMMIT() asm volatile("cp.async.commit_group;" ::: "memory")
#define CP_WAIT1()  asm volatile("cp.async.wait_group 1;" ::: "memory")

__device__ __forceinline__ uint32_t lds32(uint32_t a) {
    uint32_t v;
    asm volatile("ld.shared.b32 %0, [%1];" : "=r"(v) : "r"(a));
    return v;
}
__device__ __forceinline__ void ldsm_x4(uint32_t (&r)[4], uint32_t a) {
    asm volatile("ldmatrix.sync.aligned.m8n8.x4.shared.b16 {%0,%1,%2,%3}, [%4];"
                 : "=r"(r[0]), "=r"(r[1]), "=r"(r[2]), "=r"(r[3]) : "r"(a));
}
__device__ __forceinline__ uint32_t f2tf32(float x) {
    uint32_t r;
    asm("cvt.rna.tf32.f32 %0, %1;" : "=r"(r) : "f"(x));
    return r;
}
__device__ __forceinline__ void mma_tf32(float (&c)[4], const uint32_t (&a)[4],
                                         uint32_t b0, uint32_t b1) {
    asm volatile(
        "mma.sync.aligned.m16n8k8.row.col.f32.tf32.tf32.f32 "
        "{%0,%1,%2,%3}, {%4,%5,%6,%7}, {%8,%9}, {%0,%1,%2,%3};"
        : "+f"(c[0]), "+f"(c[1]), "+f"(c[2]), "+f"(c[3])
        : "r"(a[0]), "r"(a[1]), "r"(a[2]), "r"(a[3]), "r"(b0), "r"(b1));
}

// ---------------------------------------------------------------------------
// Tile 64x128, K-chunk 32, 256 threads (8 warps: 2M x 4N, 32x32 per warp).
// Smem/stage: A non-trans [64][36w]=9216B; A trans [32][68w]=8704B;
//             B n-major [128][36w]=18432B. 3 stages -> <=83KB => 2 CTAs/SM.
// A_CVT: A gmem is raw fp32; cvt.rna.tf32 applied after fragment load.
// z decomposition: zb = blockIdx.z % nz (batch/type), sp = blockIdx.z / nz.
// EPI 0: C=acc | 1: relu(acc+bias) | 2: C (init? = : +=) gate*(acc+bias)
// Requires N==128*gridDim.y, M%4==0, K%4==0, niter>=2.
// ---------------------------------------------------------------------------
template <int EPI, bool TRANS_A, bool A_CVT, bool OUT_TF32>
__global__ __launch_bounds__(256, 2)
void gemm_tf32(const uint32_t* __restrict__ A, const uint32_t* __restrict__ BT,
               void* __restrict__ Cv, int M, int N, int K,
               long sA, long sB, long sC,
               long aSplit, long bSplit, long cSplit, int nz,
               int lda, int ldb, int ldc,
               const float* __restrict__ bias, long biasZ,
               const float* __restrict__ gate,
               int gidx, int gld, int init_flag)
{
    constexpr int AS_BYTES = TRANS_A ? 32 * 272 : 64 * 144;
    constexpr int BS_BYTES = 128 * 144;

    extern __shared__ __align__(16) char dyn[];
    const uint32_t as0 = smem_u32(dyn);
    const uint32_t bs0 = as0 + 3 * AS_BYTES;

    const int tid = threadIdx.x;
    const int warp = tid >> 5, lane = tid & 31;
    const int wm = warp & 1, wn = warp >> 1;        // 2M x 4N
    const int m_w = wm * 32, n_w = wn * 32;
    const int g = lane >> 2, t = lane & 3;

    const int zb = blockIdx.z % nz;
    const int sp = blockIdx.z / nz;
    A  += zb * sA + sp * aSplit;
    BT += zb * sB + sp * bSplit;
    bias += zb * biasZ;
    const long cbase = zb * sC + sp * cSplit;

    const long m0 = (long)blockIdx.x * 64;
    const int  n0 = blockIdx.y * 128;

    const int niter = (K + 31) / 32;

    float acc[2][4][4];
#pragma unroll
    for (int a = 0; a < 2; a++)
#pragma unroll
        for (int b = 0; b < 4; b++)
#pragma unroll
            for (int c = 0; c < 4; c++) acc[a][b][c] = 0.f;

    auto issue = [&](int it, int stage) {
        const long k0 = (long)it * 32;
        if constexpr (!TRANS_A) {
            // A: 64 rows x 8 f4 = 512 chunks; 2 passes of 256
#pragma unroll
            for (int p = 0; p < 2; p++) {
                const int ch = tid + p * 256;
                const int row = ch >> 3, c = ch & 7;
                const long gm = m0 + row, gk = k0 + c * 4;
                const uint32_t ok = (gm < M && gk < K);
                const uint32_t* src = A + (ok ? gm * (long)lda + gk : 0);
                cpasync16(as0 + stage * AS_BYTES + row * 144 + c * 16,
                          src, ok ? 16u : 0u);
            }
        } else {
            // A: 32 k x 16 m4 = 512 chunks; 2 passes of 256
#pragma unroll
            for (int p = 0; p < 2; p++) {
                const int ch = tid + p * 256;
                const int kr = ch >> 4, m4 = ch & 15;
                const long gk = k0 + kr, gm = m0 + m4 * 4;
                const uint32_t ok = (gk < K && gm < M);
                const uint32_t* src = A + (ok ? gk * (long)lda + gm : 0);
                cpasync16(as0 + stage * AS_BYTES + kr * 272 + m4 * 16,
                          src, ok ? 16u : 0u);
            }
        }
        // B: 128 n x 8 f4 = 1024 chunks; 4 passes of 256
#pragma unroll
        for (int p = 0; p < 4; p++) {
            const int ch = tid + p * 256;
            const int r = ch >> 3, c = ch & 7;
            const long gk = k0 + c * 4;
            const uint32_t ok = (gk < K);
            const uint32_t* src = BT + (ok ? (long)(n0 + r) * ldb + gk : 0);
            cpasync16(bs0 + stage * BS_BYTES + r * 144 + c * 16,
                      src, ok ? 16u : 0u);
        }
        CP_COMMIT();
    };

    auto compute = [&](int stage) {
        const uint32_t as = as0 + stage * AS_BYTES;
        const uint32_t bs = bs0 + stage * BS_BYTES;
#pragma unroll
        for (int ks = 0; ks < 32; ks += 8) {
            uint32_t a[2][4], b[4][2];
            if constexpr (!TRANS_A) {
#pragma unroll
                for (int mt = 0; mt < 2; mt++) {
                    const uint32_t addr = as +
                        (m_w + mt * 16 + (lane & 15)) * 144 +
                        ks * 4 + ((lane >> 4) << 4);
                    ldsm_x4(a[mt], addr);
                }
            } else {
                const uint32_t base = as + (ks + t) * 272 + (m_w + g) * 4;
#pragma unroll
                for (int mt = 0; mt < 2; mt++) {
                    const uint32_t ab = base + mt * 64;
                    a[mt][0] = lds32(ab);
                    a[mt][1] = lds32(ab + 32);
                    a[mt][2] = lds32(ab + 4 * 272);
                    a[mt][3] = lds32(ab + 4 * 272 + 32);
                }
            }
            if constexpr (A_CVT) {
#pragma unroll
                for (int mt = 0; mt < 2; mt++)
#pragma unroll
                    for (int q = 0; q < 4; q++)
                        a[mt][q] = f2tf32(__uint_as_float(a[mt][q]));
            }
#pragma unroll
            for (int np = 0; np < 2; np++) {
                uint32_t r4[4];
                const uint32_t addr = bs +
                    (n_w + np * 16 + ((lane >> 4) << 3) + (lane & 7)) * 144 +
                    ks * 4 + (((lane >> 3) & 1) << 4);
                ldsm_x4(r4, addr);
                b[np * 2][0] = r4[0];
                b[np * 2][1] = r4[1];
                b[np * 2 + 1][0] = r4[2];
                b[np * 2 + 1][1] = r4[3];
            }
#pragma unroll
            for (int mt = 0; mt < 2; mt++)
#pragma unroll
                for (int nt = 0; nt < 4; nt++)
                    mma_tf32(acc[mt][nt], a[mt], b[nt][0], b[nt][1]);
        }
    };

    issue(0, 0);
    issue(1, 1);

    for (int it = 0; it < niter; it++) {
        CP_WAIT1();
        __syncthreads();
        if (it + 2 < niter) {
            issue(it + 2, (it + 2) % 3);
        } else {
            // TAIL-RACE FIX: keep the committed-group count at it+2 so
            // wait_group 1 always guarantees group `it` (the chunk being
            // computed) is complete. Without this, the last chunk races
            // its own cp.async completion (manifested at 2 CTAs/SM).
            CP_COMMIT();
        }
        compute(it % 3);
    }

    // ---------------- epilogue ----------------
    const int tg = t * 2;
#pragma unroll
    for (int mt = 0; mt < 2; mt++) {
#pragma unroll
        for (int h = 0; h < 2; h++) {
            const long r = m0 + m_w + mt * 16 + g + h * 8;
            if (r >= M) continue;
            float gt = 0.f;
            if (EPI == 2) gt = gate[r * (long)gld + gidx];
#pragma unroll
            for (int nt = 0; nt < 4; nt++) {
                const int col = n_w + nt * 8 + tg;   // [0,128)
                float v0 = acc[mt][nt][h * 2 + 0];
                float v1 = acc[mt][nt][h * 2 + 1];
                if (EPI == 1) {
                    float2 bb = *(const float2*)(bias + n0 + col);
                    v0 = fmaxf(v0 + bb.x, 0.f);
                    v1 = fmaxf(v1 + bb.y, 0.f);
                } else if (EPI == 2) {
                    float2 bb = *(const float2*)(bias + n0 + col);
                    v0 = gt * (v0 + bb.x);
                    v1 = gt * (v1 + bb.y);
                }
                if constexpr (OUT_TF32) {
                    uint32_t* p = (uint32_t*)Cv + cbase + r * (long)ldc + n0 + col;
                    uint2 o;
                    o.x = f2tf32(v0);
                    o.y = f2tf32(v1);
                    *reinterpret_cast<uint2*>(p) = o;
                } else {
                    float* p = (float*)Cv + cbase + r * (long)ldc + n0 + col;
                    if (EPI == 2 && !init_flag) {
                        float2 o = *(const float2*)p;
                        v0 += o.x; v1 += o.y;
                    }
                    *reinterpret_cast<float2*>(p) = make_float2(v0, v1);
                }
            }
        }
    }
}

// ---------------------------------------------------------------------------
// in fp32 [z][R][C] -> out tf32 [z][C][R]   (C % 32 == 0; R guarded)
__global__ void trans_cvt_kernel(const float* __restrict__ src,
                                 uint32_t* __restrict__ dst,
                                 int R, int C, long sIn, long sOut)
{
    __shared__ float tbuf[32][33];
    const int r0 = blockIdx.x * 32, c0 = blockIdx.y * 32, z = blockIdx.z;
    const int tx = threadIdx.x, ty = threadIdx.y;
    const float* in = src + (long)z * sIn;
#pragma unroll
    for (int i = ty; i < 32; i += 8) {
        const int r = r0 + i;
        tbuf[i][tx] = (r < R) ? in[(long)r * C + c0 + tx] : 0.f;
    }
    __syncthreads();
    uint32_t* outp = dst + (long)z * sOut;
#pragma unroll
    for (int i = ty; i < 32; i += 8) {
        const int r = r0 + tx;
        if (r < R) outp[(long)(c0 + i) * R + r] = f2tf32(tbuf[tx][i]);
    }
}

// out[b,n,0:256] = sum_s part[s][b][n][:]
__global__ void reduce_part_kernel(const float* __restrict__ part,
                                   float* __restrict__ out, int total4)
{
    const int idx = blockIdx.x * blockDim.x + threadIdx.x;
    if (idx >= total4) return;
    const int d4 = idx & 63;
    const int bn = idx >> 6;
    const long stride4 = 4L * 2000 * 64;
    float4 s = ((const float4*)part)[idx];
#pragma unroll
    for (int sp = 1; sp < 4; sp++) {
        float4 v = ((const float4*)part)[idx + sp * stride4];
        s.x += v.x; s.y += v.y; s.z += v.z; s.w += v.w;
    }
    ((float4*)out)[(long)bn * 128 + d4] = s;
}

// out[b,n,256:512] = ori[b,n,:]
__global__ void concat_ori_kernel(const float* __restrict__ ori,
                                  float* __restrict__ out, int total4)
{
    int idx = blockIdx.x * blockDim.x + threadIdx.x;
    if (idx >= total4) return;
    int d4 = idx & 63;
    int bn = idx >> 6;
    float4 v = ((const float4*)ori)[idx];
    ((float4*)out)[(long)bn * 128 + 64 + d4] = v;
}

// ---------------------------------------------------------------------------
extern "C" void kernel_launch(void* const* d_in, const int* in_sizes, int n_in,
                              void* d_out, int out_size)
{
    const float* ed  = (const float*)d_in[0];   // [4,8000,5]
    const float* H   = (const float*)d_in[1];   // [4,8000,2000]
    const float* ori = (const float*)d_in[2];   // [4,2000,256]
    const float* W1  = (const float*)d_in[3];   // [5,256,128]
    const float* b1  = (const float*)d_in[4];   // [5,128]
    const float* W2  = (const float*)d_in[5];   // [5,128,256]
    const float* b2  = (const float*)d_in[6];   // [5,256]
    float* out = (float*)d_out;                 // [4,2000,512]

    uint32_t *oriT, *W1T, *W2T, *edges, *ht5, *efT;
    float *ef, *part;
    cudaGetSymbolAddress((void**)&oriT, g_oriT);
    cudaGetSymbolAddress((void**)&W1T, g_W1T);
    cudaGetSymbolAddress((void**)&W2T, g_W2T);
    cudaGetSymbolAddress((void**)&edges, g_edges);
    cudaGetSymbolAddress((void**)&ht5, g_ht5);
    cudaGetSymbolAddress((void**)&ef, g_ef);
    cudaGetSymbolAddress((void**)&efT, g_efT);
    cudaGetSymbolAddress((void**)&part, g_part);

    const int SM_NT = 3 * (64 * 144 + 128 * 144);   // 82944
    const int SM_T  = 3 * (32 * 272 + 128 * 144);   // 81408
    cudaFuncSetAttribute(gemm_tf32<0, false, true, true>,
                         cudaFuncAttributeMaxDynamicSharedMemorySize, SM_NT);
    cudaFuncSetAttribute(gemm_tf32<1, false, false, true>,
                         cudaFuncAttributeMaxDynamicSharedMemorySize, SM_NT);
    cudaFuncSetAttribute(gemm_tf32<2, false, false, false>,
                         cudaFuncAttributeMaxDynamicSharedMemorySize, SM_NT);
    cudaFuncSetAttribute(gemm_tf32<0, true, true, false>,
                         cudaFuncAttributeMaxDynamicSharedMemorySize, SM_T);

    // 0) transpose+convert B operands to n-major tf32
    trans_cvt_kernel<<<dim3(63, 8, 4), dim3(32, 8)>>>(
        ori, oriT, 2000, 256, 2000L * 256, 2000L * 256);
    trans_cvt_kernel<<<dim3(8, 4, 5), dim3(32, 8)>>>(
        W1, W1T, 256, 128, 256L * 128, 256L * 128);
    trans_cvt_kernel<<<dim3(4, 8, 5), dim3(32, 8)>>>(
        W2, W2T, 128, 256, 128L * 256, 128L * 256);

    // 1) edges = H @ ori   (A = H fp32 + in-loop cvt; B = oriT; tf32 out)
    gemm_tf32<0, false, true, true><<<dim3(125, 2, 4), 256, SM_NT>>>(
        (const uint32_t*)H, oriT, edges, 8000, 256, 2000,
        8000L * 2000, 256L * 2000, 8000L * 256, 0, 0, 0, 4,
        2000, 2000, 256, nullptr, 0, nullptr, 0, 0, 0);

    // 2a) MLP1 for all 5 types in one launch (z = t)
    gemm_tf32<1, false, false, true><<<dim3(500, 1, 5), 256, SM_NT>>>(
        edges, W1T, ht5, 32000, 128, 256,
        0, 128L * 256, 32000L * 128, 0, 0, 0, 5,
        256, 256, 128, b1, 128, nullptr, 0, 0, 0);

    // 2b) MLP2 per type (sequential: ef accumulation)
    for (int t = 0; t < 5; t++) {
        gemm_tf32<2, false, false, false><<<dim3(500, 2, 1), 256, SM_NT>>>(
            ht5 + (long)t * 32000 * 128, W2T + (long)t * 256 * 128, ef,
            32000, 256, 128,
            0, 0, 0, 0, 0, 0, 1,
            128, 128, 256, b2 + t * 256, 0, ed, t, 5, (t == 0) ? 1 : 0);
    }

    // 3) efT = transpose+convert(ef) per batch: [8000,256] -> [256,8000]
    trans_cvt_kernel<<<dim3(250, 8, 4), dim3(32, 8)>>>(
        ef, efT, 8000, 256, 8000L * 256, 8000L * 256);

    // 4) part[s] = H[ks]^T @ ef[ks]  (split-K x4; A = H fp32 TRANS + cvt)
    gemm_tf32<0, true, true, false><<<dim3(32, 2, 16), 256, SM_T>>>(
        (const uint32_t*)H, efT, part, 2000, 256, 2000,
        8000L * 2000, 256L * 8000, 2000L * 256,
        2000L * 2000, 2000, 4L * 2000 * 256, 4,
        2000, 8000, 256, nullptr, 0, nullptr, 0, 0, 0);

    // 5) out[:, :, :256] = sum_s part[s] ; out[:, :, 256:] = ori
    reduce_part_kernel<<<(4 * 2000 * 64 + 255) / 256, 256>>>(
        part, out, 4 * 2000 * 64);
    concat_ori_kernel<<<(4 * 2000 * 64 + 255) / 256, 256>>>(
        ori, out, 4 * 2000 * 64);
}

// round 12
// speedup vs baseline: 1.2673x; 1.0090x over previous
#include <cuda_runtime.h>
#include <cstdint>

// ---------------------------------------------------------------------------
// edge_aggregation (B=4, E=8000, N=2000, D=256, HID=128, T=5)
// tf32 mma.sync.m16n8k8 + cp.async 3-stage pipeline + ldmatrix fragments.
// Round 12: (a) intra-chunk fragment double-buffering (hide ldsm latency),
// (b) pointer-increment loaders (kill 64-bit address IMAD chains),
// (c) fused finalize kernel. Geometry: 256-thr CTAs, 64x128 tiles, 2 CTAs/SM.
//   edges = H @ ori                      GEMM1  M=8000 N=256 K=2000  x4
//   h     = relu(edges@W1[t]+b1)         MLP1   M=32000 N=128 K=256  x5 (one launch)
//   ef   += gate_t*(h@W2[t]+b2)          MLP2   M=32000 N=256 K=128  x5
//   out[:, :256] = H^T @ ef              GEMM3  M=2000 N=256 K=8000  split-K x4
//   out[:, 256:] = ori
// ---------------------------------------------------------------------------

__device__ uint32_t g_oriT[4 * 256 * 2000];      // [b][d][n] tf32
__device__ uint32_t g_W1T[5 * 128 * 256];        // [t][h][d] tf32
__device__ uint32_t g_W2T[5 * 256 * 128];        // [t][d][h] tf32
__device__ uint32_t g_edges[32000 * 256];        // tf32 (GEMM1 out)
__device__ uint32_t g_ht5[5L * 32000 * 128];     // tf32 (MLP1 out, per type)
__device__ float    g_ef[32000 * 256];           // fp32 accumulator
__device__ uint32_t g_efT[4 * 256 * 8000];       // [b][d][e] tf32
__device__ float    g_part[4L * 4 * 2000 * 256]; // split-K partials

// ---------------- PTX helpers ----------------
__device__ __forceinline__ uint32_t smem_u32(const void* p) {
    uint32_t a;
    asm("{ .reg .u64 t; cvta.to.shared.u64 t, %1; cvt.u32.u64 %0, t; }"
        : "=r"(a) : "l"(p));
    return a;
}
__device__ __forceinline__ void cpasync16(uint32_t dst, const void* src, uint32_t sz) {
    asm volatile("cp.async.cg.shared.global [%0], [%1], 16, %2;"
                 :: "r"(dst), "l"(src), "r"(sz) : "memory");
}
#define CP_COMMIT() asm volatile("cp.async.commit_group;" ::: "memory")
#define CP_WAIT1()  asm volatile("cp.async.wait_group 1;" ::: "memory")

__device__ __forceinline__ uint32_t lds32(uint32_t a) {
    uint32_t v;
    asm volatile("ld.shared.b32 %0, [%1];" : "=r"(v) : "r"(a));
    return v;
}
__device__ __forceinline__ void ldsm_x4(uint32_t (&r)[4], uint32_t a) {
    asm volatile("ldmatrix.sync.aligned.m8n8.x4.shared.b16 {%0,%1,%2,%3}, [%4];"
                 : "=r"(r[0]), "=r"(r[1]), "=r"(r[2]), "=r"(r[3]) : "r"(a));
}
__device__ __forceinline__ uint32_t f2tf32(float x) {
    uint32_t r;
    asm("cvt.rna.tf32.f32 %0, %1;" : "=r"(r) : "f"(x));
    return r;
}
__device__ __forceinline__ void mma_tf32(float (&c)[4], const uint32_t (&a)[4],
                                         uint32_t b0, uint32_t b1) {
    asm volatile(
        "mma.sync.aligned.m16n8k8.row.col.f32.tf32.tf32.f32 "
        "{%0,%1,%2,%3}, {%4,%5,%6,%7}, {%8,%9}, {%0,%1,%2,%3};"
        : "+f"(c[0]), "+f"(c[1]), "+f"(c[2]), "+f"(c[3])
        : "r"(a[0]), "r"(a[1]), "r"(a[2]), "r"(a[3]), "r"(b0), "r"(b1));
}

// ---------------------------------------------------------------------------
// Tile 64x128, K-chunk 32, 256 threads (8 warps: 2M x 4N, 32x32 per warp).
// Smem/stage: A non-trans [64][36w]=9216B; A trans [32][68w]=8704B;
//             B n-major [128][36w]=18432B. 3 stages => 2 CTAs/SM.
// Loaders use persistent per-thread pointers advanced by constants (issue()
// calls are strictly sequential in `it`). Tail iterations commit an empty
// cp.async group (round-11 race fix). Fragments double-buffered across the
// 4 k-steps of each chunk to hide ldsm/lds latency under mma.
// EPI 0: C=acc | 1: relu(acc+bias) | 2: C (init? = : +=) gate*(acc+bias)
// Requires N==128*gridDim.y, M%4==0, K%4==0, niter>=2.
// ---------------------------------------------------------------------------
template <int EPI, bool TRANS_A, bool A_CVT, bool OUT_TF32>
__global__ __launch_bounds__(256, 2)
void gemm_tf32(const uint32_t* __restrict__ A, const uint32_t* __restrict__ BT,
               void* __restrict__ Cv, int M, int N, int K,
               long sA, long sB, long sC,
               long aSplit, long bSplit, long cSplit, int nz,
               int lda, int ldb, int ldc,
               const float* __restrict__ bias, long biasZ,
               const float* __restrict__ gate,
               int gidx, int gld, int init_flag)
{
    constexpr int AS_BYTES = TRANS_A ? 32 * 272 : 64 * 144;
    constexpr int BS_BYTES = 128 * 144;

    extern __shared__ __align__(16) char dyn[];
    const uint32_t as0 = smem_u32(dyn);
    const uint32_t bs0 = as0 + 3 * AS_BYTES;

    const int tid = threadIdx.x;
    const int warp = tid >> 5, lane = tid & 31;
    const int wm = warp & 1, wn = warp >> 1;        // 2M x 4N
    const int m_w = wm * 32, n_w = wn * 32;
    const int g = lane >> 2, t = lane & 3;

    const int zb = blockIdx.z % nz;
    const int sp = blockIdx.z / nz;
    A  += zb * sA + sp * aSplit;
    BT += zb * sB + sp * bSplit;
    bias += zb * biasZ;
    const long cbase = zb * sC + sp * cSplit;

    const long m0 = (long)blockIdx.x * 64;
    const int  n0 = blockIdx.y * 128;

    const int niter = (K + 31) / 32;

    float acc[2][4][4];
#pragma unroll
    for (int a = 0; a < 2; a++)
#pragma unroll
        for (int b = 0; b < 4; b++)
#pragma unroll
            for (int c = 0; c < 4; c++) acc[a][b][c] = 0.f;

    // ---- persistent loader state (pointer-increment; no per-chunk IMADs) ----
    // A loader
    const uint32_t* pA[2];
    uint32_t aDst[2];
    int aCC[2];           // k-offset within chunk for the guard
    bool aMok[2];
    int aStep;            // words to advance per chunk
    if constexpr (!TRANS_A) {
        aStep = 32;
#pragma unroll
        for (int p = 0; p < 2; p++) {
            const int ch = tid + p * 256;
            const int row = ch >> 3, c = ch & 7;
            const long gm = m0 + row;
            aMok[p] = (gm < M);
            aCC[p] = c * 4;
            pA[p] = A + (aMok[p] ? gm * (long)lda + c * 4 : 0);
            aDst[p] = as0 + row * 144 + c * 16;
        }
    } else {
        aStep = 32 * lda;
#pragma unroll
        for (int p = 0; p < 2; p++) {
            const int ch = tid + p * 256;
            const int kr = ch >> 4, m4 = ch & 15;
            const long gm = m0 + m4 * 4;
            aMok[p] = (gm < M);
            aCC[p] = kr;
            pA[p] = A + (aMok[p] ? (long)kr * lda + gm : 0);
            aDst[p] = as0 + kr * 272 + m4 * 16;
        }
    }
    // B loader
    const uint32_t* pB[4];
    uint32_t bDst[4];
    int bCC[4];
#pragma unroll
    for (int p = 0; p < 4; p++) {
        const int ch = tid + p * 256;
        const int r = ch >> 3, c = ch & 7;
        bCC[p] = c * 4;
        pB[p] = BT + (long)(n0 + r) * ldb + c * 4;
        bDst[p] = bs0 + r * 144 + c * 16;
    }

    auto issue = [&](int it, int stage) {
        const int k0 = it * 32;
        const uint32_t aOff = stage * AS_BYTES;
        const uint32_t bOff = stage * BS_BYTES;
#pragma unroll
        for (int p = 0; p < 2; p++) {
            const bool ok = aMok[p] && (k0 + aCC[p] < K);
            cpasync16(aDst[p] + aOff, ok ? pA[p] : A, ok ? 16u : 0u);
            pA[p] += aStep;
        }
#pragma unroll
        for (int p = 0; p < 4; p++) {
            const bool ok = (k0 + bCC[p] < K);
            cpasync16(bDst[p] + bOff, ok ? pB[p] : BT, ok ? 16u : 0u);
            pB[p] += 32;
        }
        CP_COMMIT();
    };

    // ---- fragment loads (ks = k-step index 0..3, i.e. k offset ks*8) ----
    auto frag_a = [&](uint32_t as, int ks, uint32_t (&a)[2][4]) {
        if constexpr (!TRANS_A) {
#pragma unroll
            for (int mt = 0; mt < 2; mt++) {
                const uint32_t addr = as +
                    (m_w + mt * 16 + (lane & 15)) * 144 +
                    ks * 32 + ((lane >> 4) << 4);
                ldsm_x4(a[mt], addr);
            }
        } else {
            const uint32_t base = as + (ks * 8 + t) * 272 + (m_w + g) * 4;
#pragma unroll
            for (int mt = 0; mt < 2; mt++) {
                const uint32_t ab = base + mt * 64;
                a[mt][0] = lds32(ab);
                a[mt][1] = lds32(ab + 32);
                a[mt][2] = lds32(ab + 4 * 272);
                a[mt][3] = lds32(ab + 4 * 272 + 32);
            }
        }
        if constexpr (A_CVT) {
#pragma unroll
            for (int mt = 0; mt < 2; mt++)
#pragma unroll
                for (int q = 0; q < 4; q++)
                    a[mt][q] = f2tf32(__uint_as_float(a[mt][q]));
        }
    };
    auto frag_b = [&](uint32_t bs, int ks, uint32_t (&b)[4][2]) {
#pragma unroll
        for (int np = 0; np < 2; np++) {
            uint32_t r4[4];
            const uint32_t addr = bs +
                (n_w + np * 16 + ((lane >> 4) << 3) + (lane & 7)) * 144 +
                ks * 32 + (((lane >> 3) & 1) << 4);
            ldsm_x4(r4, addr);
            b[np * 2][0] = r4[0];
            b[np * 2][1] = r4[1];
            b[np * 2 + 1][0] = r4[2];
            b[np * 2 + 1][1] = r4[3];
        }
    };

    auto compute = [&](int stage) {
        const uint32_t as = as0 + stage * AS_BYTES;
        const uint32_t bs = bs0 + stage * BS_BYTES;
        uint32_t a[2][2][4], b[2][4][2];
        frag_a(as, 0, a[0]);
        frag_b(bs, 0, b[0]);
#pragma unroll
        for (int ks = 0; ks < 4; ks++) {
            const int cur = ks & 1, nxt = cur ^ 1;
            if (ks < 3) {                 // prefetch next k-step's fragments
                frag_a(as, ks + 1, a[nxt]);
                frag_b(bs, ks + 1, b[nxt]);
            }
#pragma unroll
            for (int mt = 0; mt < 2; mt++)
#pragma unroll
                for (int nt = 0; nt < 4; nt++)
                    mma_tf32(acc[mt][nt], a[cur][mt],
                             b[cur][nt][0], b[cur][nt][1]);
        }
    };

    issue(0, 0);
    issue(1, 1);

    for (int it = 0; it < niter; it++) {
        CP_WAIT1();
        __syncthreads();
        if (it + 2 < niter) {
            issue(it + 2, (it + 2) % 3);
        } else {
            // Tail-race fix: keep committed-group count at it+2 so
            // wait_group 1 guarantees the chunk being computed is complete.
            CP_COMMIT();
        }
        compute(it % 3);
    }

    // ---------------- epilogue ----------------
    const int tg = t * 2;
#pragma unroll
    for (int mt = 0; mt < 2; mt++) {
#pragma unroll
        for (int h = 0; h < 2; h++) {
            const long r = m0 + m_w + mt * 16 + g + h * 8;
            if (r >= M) continue;
            float gt = 0.f;
            if (EPI == 2) gt = gate[r * (long)gld + gidx];
#pragma unroll
            for (int nt = 0; nt < 4; nt++) {
                const int col = n_w + nt * 8 + tg;   // [0,128)
                float v0 = acc[mt][nt][h * 2 + 0];
                float v1 = acc[mt][nt][h * 2 + 1];
                if (EPI == 1) {
                    float2 bb = *(const float2*)(bias + n0 + col);
                    v0 = fmaxf(v0 + bb.x, 0.f);
                    v1 = fmaxf(v1 + bb.y, 0.f);
                } else if (EPI == 2) {
                    float2 bb = *(const float2*)(bias + n0 + col);
                    v0 = gt * (v0 + bb.x);
                    v1 = gt * (v1 + bb.y);
                }
                if constexpr (OUT_TF32) {
                    uint32_t* p = (uint32_t*)Cv + cbase + r * (long)ldc + n0 + col;
                    uint2 o;
                    o.x = f2tf32(v0);
                    o.y = f2tf32(v1);
                    *reinterpret_cast<uint2*>(p) = o;
                } else {
                    float* p = (float*)Cv + cbase + r * (long)ldc + n0 + col;
                    if (EPI == 2 && !init_flag) {
                        float2 o = *(const float2*)p;
                        v0 += o.x; v1 += o.y;
                    }
                    *reinterpret_cast<float2*>(p) = make_float2(v0, v1);
                }
            }
        }
    }
}

// ---------------------------------------------------------------------------
// in fp32 [z][R][C] -> out tf32 [z][C][R]   (C % 32 == 0; R guarded)
__global__ void trans_cvt_kernel(const float* __restrict__ src,
                                 uint32_t* __restrict__ dst,
                                 int R, int C, long sIn, long sOut)
{
    __shared__ float tbuf[32][33];
    const int r0 = blockIdx.x * 32, c0 = blockIdx.y * 32, z = blockIdx.z;
    const int tx = threadIdx.x, ty = threadIdx.y;
    const float* in = src + (long)z * sIn;
#pragma unroll
    for (int i = ty; i < 32; i += 8) {
        const int r = r0 + i;
        tbuf[i][tx] = (r < R) ? in[(long)r * C + c0 + tx] : 0.f;
    }
    __syncthreads();
    uint32_t* outp = dst + (long)z * sOut;
#pragma unroll
    for (int i = ty; i < 32; i += 8) {
        const int r = r0 + tx;
        if (r < R) outp[(long)(c0 + i) * R + r] = f2tf32(tbuf[tx][i]);
    }
}

// out[b,n,0:256] = sum_s part[s][b][n][:]; out[b,n,256:512] = ori[b,n,:]
__global__ void finalize_kernel(const float* __restrict__ part,
                                const float* __restrict__ ori,
                                float* __restrict__ out, int total4)
{
    const int idx = blockIdx.x * blockDim.x + threadIdx.x;
    if (idx >= total4) return;
    const int d4 = idx & 63;
    const int bn = idx >> 6;
    const long stride4 = 4L * 2000 * 64;
    float4 s = ((const float4*)part)[idx];
#pragma unroll
    for (int sp = 1; sp < 4; sp++) {
        float4 v = ((const float4*)part)[idx + sp * stride4];
        s.x += v.x; s.y += v.y; s.z += v.z; s.w += v.w;
    }
    ((float4*)out)[(long)bn * 128 + d4] = s;
    float4 o = ((const float4*)ori)[idx];
    ((float4*)out)[(long)bn * 128 + 64 + d4] = o;
}

// ---------------------------------------------------------------------------
extern "C" void kernel_launch(void* const* d_in, const int* in_sizes, int n_in,
                              void* d_out, int out_size)
{
    const float* ed  = (const float*)d_in[0];   // [4,8000,5]
    const float* H   = (const float*)d_in[1];   // [4,8000,2000]
    const float* ori = (const float*)d_in[2];   // [4,2000,256]
    const float* W1  = (const float*)d_in[3];   // [5,256,128]
    const float* b1  = (const float*)d_in[4];   // [5,128]
    const float* W2  = (const float*)d_in[5];   // [5,128,256]
    const float* b2  = (const float*)d_in[6];   // [5,256]
    float* out = (float*)d_out;                 // [4,2000,512]

    uint32_t *oriT, *W1T, *W2T, *edges, *ht5, *efT;
    float *ef, *part;
    cudaGetSymbolAddress((void**)&oriT, g_oriT);
    cudaGetSymbolAddress((void**)&W1T, g_W1T);
    cudaGetSymbolAddress((void**)&W2T, g_W2T);
    cudaGetSymbolAddress((void**)&edges, g_edges);
    cudaGetSymbolAddress((void**)&ht5, g_ht5);
    cudaGetSymbolAddress((void**)&ef, g_ef);
    cudaGetSymbolAddress((void**)&efT, g_efT);
    cudaGetSymbolAddress((void**)&part, g_part);

    const int SM_NT = 3 * (64 * 144 + 128 * 144);   // 82944
    const int SM_T  = 3 * (32 * 272 + 128 * 144);   // 81408
    cudaFuncSetAttribute(gemm_tf32<0, false, true, true>,
                         cudaFuncAttributeMaxDynamicSharedMemorySize, SM_NT);
    cudaFuncSetAttribute(gemm_tf32<1, false, false, true>,
                         cudaFuncAttributeMaxDynamicSharedMemorySize, SM_NT);
    cudaFuncSetAttribute(gemm_tf32<2, false, false, false>,
                         cudaFuncAttributeMaxDynamicSharedMemorySize, SM_NT);
    cudaFuncSetAttribute(gemm_tf32<0, true, true, false>,
                         cudaFuncAttributeMaxDynamicSharedMemorySize, SM_T);

    // 0) transpose+convert B operands to n-major tf32
    trans_cvt_kernel<<<dim3(63, 8, 4), dim3(32, 8)>>>(
        ori, oriT, 2000, 256, 2000L * 256, 2000L * 256);
    trans_cvt_kernel<<<dim3(8, 4, 5), dim3(32, 8)>>>(
        W1, W1T, 256, 128, 256L * 128, 256L * 128);
    trans_cvt_kernel<<<dim3(4, 8, 5), dim3(32, 8)>>>(
        W2, W2T, 128, 256, 128L * 256, 128L * 256);

    // 1) edges = H @ ori   (A = H fp32 + in-loop cvt; B = oriT; tf32 out)
    gemm_tf32<0, false, true, true><<<dim3(125, 2, 4), 256, SM_NT>>>(
        (const uint32_t*)H, oriT, edges, 8000, 256, 2000,
        8000L * 2000, 256L * 2000, 8000L * 256, 0, 0, 0, 4,
        2000, 2000, 256, nullptr, 0, nullptr, 0, 0, 0);

    // 2a) MLP1 for all 5 types in one launch (z = t)
    gemm_tf32<1, false, false, true><<<dim3(500, 1, 5), 256, SM_NT>>>(
        edges, W1T, ht5, 32000, 128, 256,
        0, 128L * 256, 32000L * 128, 0, 0, 0, 5,
        256, 256, 128, b1, 128, nullptr, 0, 0, 0);

    // 2b) MLP2 per type (sequential: ef accumulation)
    for (int t = 0; t < 5; t++) {
        gemm_tf32<2, false, false, false><<<dim3(500, 2, 1), 256, SM_NT>>>(
            ht5 + (long)t * 32000 * 128, W2T + (long)t * 256 * 128, ef,
            32000, 256, 128,
            0, 0, 0, 0, 0, 0, 1,
            128, 128, 256, b2 + t * 256, 0, ed, t, 5, (t == 0) ? 1 : 0);
    }

    // 3) efT = transpose+convert(ef) per batch: [8000,256] -> [256,8000]
    trans_cvt_kernel<<<dim3(250, 8, 4), dim3(32, 8)>>>(
        ef, efT, 8000, 256, 8000L * 256, 8000L * 256);

    // 4) part[s] = H[ks]^T @ ef[ks]  (split-K x4; A = H fp32 TRANS + cvt)
    gemm_tf32<0, true, true, false><<<dim3(32, 2, 16), 256, SM_T>>>(
        (const uint32_t*)H, efT, part, 2000, 256, 2000,
        8000L * 2000, 256L * 8000, 2000L * 256,
        2000L * 2000, 2000, 4L * 2000 * 256, 4,
        2000, 8000, 256, nullptr, 0, nullptr, 0, 0, 0);

    // 5) out = [reduce(part), ori]
    finalize_kernel<<<(4 * 2000 * 64 + 255) / 256, 256>>>(
        part, ori, out, 4 * 2000 * 64);
}

// round 13
// speedup vs baseline: 1.3925x; 1.0988x over previous
#include <cuda_runtime.h>
#include <cstdint>

// ---------------------------------------------------------------------------
// edge_aggregation (B=4, E=8000, N=2000, D=256, HID=128, T=5)
// tf32 mma.sync.m16n8k8 + cp.async + ldmatrix fragments.
// Round 13: 2-stage pipeline (55KB smem/CTA) + __launch_bounds__(256,3)
// -> 3 CTAs/SM, 24 warps/SM. Single-buffered fragments (r12 double-buffer
// was neutral; freed regs pay for the occupancy cap).
//   edges = H @ ori                      GEMM1  M=8000 N=256 K=2000  x4
//   h     = relu(edges@W1[t]+b1)         MLP1   M=32000 N=128 K=256  x5 (one launch)
//   ef   += gate_t*(h@W2[t]+b2)          MLP2   M=32000 N=256 K=128  x5
//   out[:, :256] = H^T @ ef              GEMM3  M=2000 N=256 K=8000  split-K x4
//   out[:, 256:] = ori
// ---------------------------------------------------------------------------

__device__ uint32_t g_oriT[4 * 256 * 2000];      // [b][d][n] tf32
__device__ uint32_t g_W1T[5 * 128 * 256];        // [t][h][d] tf32
__device__ uint32_t g_W2T[5 * 256 * 128];        // [t][d][h] tf32
__device__ uint32_t g_edges[32000 * 256];        // tf32 (GEMM1 out)
__device__ uint32_t g_ht5[5L * 32000 * 128];     // tf32 (MLP1 out, per type)
__device__ float    g_ef[32000 * 256];           // fp32 accumulator
__device__ uint32_t g_efT[4 * 256 * 8000];       // [b][d][e] tf32
__device__ float    g_part[4L * 4 * 2000 * 256]; // split-K partials

// ---------------- PTX helpers ----------------
__device__ __forceinline__ uint32_t smem_u32(const void* p) {
    uint32_t a;
    asm("{ .reg .u64 t; cvta.to.shared.u64 t, %1; cvt.u32.u64 %0, t; }"
        : "=r"(a) : "l"(p));
    return a;
}
__device__ __forceinline__ void cpasync16(uint32_t dst, const void* src, uint32_t sz) {
    asm volatile("cp.async.cg.shared.global [%0], [%1], 16, %2;"
                 :: "r"(dst), "l"(src), "r"(sz) : "memory");
}
#define CP_COMMIT() asm volatile("cp.async.commit_group;" ::: "memory")
#define CP_WAIT1()  asm volatile("cp.async.wait_group 1;" ::: "memory")

__device__ __forceinline__ uint32_t lds32(uint32_t a) {
    uint32_t v;
    asm volatile("ld.shared.b32 %0, [%1];" : "=r"(v) : "r"(a));
    return v;
}
__device__ __forceinline__ void ldsm_x4(uint32_t (&r)[4], uint32_t a) {
    asm volatile("ldmatrix.sync.aligned.m8n8.x4.shared.b16 {%0,%1,%2,%3}, [%4];"
                 : "=r"(r[0]), "=r"(r[1]), "=r"(r[2]), "=r"(r[3]) : "r"(a));
}
__device__ __forceinline__ uint32_t f2tf32(float x) {
    uint32_t r;
    asm("cvt.rna.tf32.f32 %0, %1;" : "=r"(r) : "f"(x));
    return r;
}
__device__ __forceinline__ void mma_tf32(float (&c)[4], const uint32_t (&a)[4],
                                         uint32_t b0, uint32_t b1) {
    asm volatile(
        "mma.sync.aligned.m16n8k8.row.col.f32.tf32.tf32.f32 "
        "{%0,%1,%2,%3}, {%4,%5,%6,%7}, {%8,%9}, {%0,%1,%2,%3};"
        : "+f"(c[0]), "+f"(c[1]), "+f"(c[2]), "+f"(c[3])
        : "r"(a[0]), "r"(a[1]), "r"(a[2]), "r"(a[3]), "r"(b0), "r"(b1));
}

// ---------------------------------------------------------------------------
// Tile 64x128, K-chunk 32, 256 threads (8 warps: 2M x 4N, 32x32 per warp).
// 2-STAGE pipeline: smem/CTA = 2*(A+B) = 55.3KB (trans: 54.3KB) => 3 CTAs/SM
// with __launch_bounds__(256,3) (85-reg cap). Two __syncthreads per chunk:
// the second prevents issue(it+2) from overwriting the buffer that other
// warps may still be computing on (classic double-buffer hazard).
// Tail iterations commit an empty cp.async group (round-11 race fix) so
// CP_WAIT1 always guarantees the chunk being computed is complete.
// A_CVT: A gmem is raw fp32; cvt.rna.tf32 applied after fragment load.
// z decomposition: zb = blockIdx.z % nz (batch/type), sp = blockIdx.z / nz.
// EPI 0: C=acc | 1: relu(acc+bias) | 2: C (init? = : +=) gate*(acc+bias)
// Requires N==128*gridDim.y, M%4==0, K%4==0, niter>=2.
// ---------------------------------------------------------------------------
template <int EPI, bool TRANS_A, bool A_CVT, bool OUT_TF32>
__global__ __launch_bounds__(256, 3)
void gemm_tf32(const uint32_t* __restrict__ A, const uint32_t* __restrict__ BT,
               void* __restrict__ Cv, int M, int N, int K,
               long sA, long sB, long sC,
               long aSplit, long bSplit, long cSplit, int nz,
               int lda, int ldb, int ldc,
               const float* __restrict__ bias, long biasZ,
               const float* __restrict__ gate,
               int gidx, int gld, int init_flag)
{
    constexpr int AS_BYTES = TRANS_A ? 32 * 272 : 64 * 144;
    constexpr int BS_BYTES = 128 * 144;

    extern __shared__ __align__(16) char dyn[];
    const uint32_t as0 = smem_u32(dyn);
    const uint32_t bs0 = as0 + 2 * AS_BYTES;

    const int tid = threadIdx.x;
    const int warp = tid >> 5, lane = tid & 31;
    const int wm = warp & 1, wn = warp >> 1;        // 2M x 4N
    const int m_w = wm * 32, n_w = wn * 32;
    const int g = lane >> 2, t = lane & 3;

    const int zb = blockIdx.z % nz;
    const int sp = blockIdx.z / nz;
    A  += zb * sA + sp * aSplit;
    BT += zb * sB + sp * bSplit;
    bias += zb * biasZ;
    const long cbase = zb * sC + sp * cSplit;

    const long m0 = (long)blockIdx.x * 64;
    const int  n0 = blockIdx.y * 128;

    const int niter = (K + 31) / 32;

    float acc[2][4][4];
#pragma unroll
    for (int a = 0; a < 2; a++)
#pragma unroll
        for (int b = 0; b < 4; b++)
#pragma unroll
            for (int c = 0; c < 4; c++) acc[a][b][c] = 0.f;

    // ---- persistent loader state (pointer-increment) ----
    const uint32_t* pA[2];
    uint32_t aDst[2];
    int aCC[2];
    bool aMok[2];
    int aStep;
    if constexpr (!TRANS_A) {
        aStep = 32;
#pragma unroll
        for (int p = 0; p < 2; p++) {
            const int ch = tid + p * 256;
            const int row = ch >> 3, c = ch & 7;
            const long gm = m0 + row;
            aMok[p] = (gm < M);
            aCC[p] = c * 4;
            pA[p] = A + (aMok[p] ? gm * (long)lda + c * 4 : 0);
            aDst[p] = as0 + row * 144 + c * 16;
        }
    } else {
        aStep = 32 * lda;
#pragma unroll
        for (int p = 0; p < 2; p++) {
            const int ch = tid + p * 256;
            const int kr = ch >> 4, m4 = ch & 15;
            const long gm = m0 + m4 * 4;
            aMok[p] = (gm < M);
            aCC[p] = kr;
            pA[p] = A + (aMok[p] ? (long)kr * lda + gm : 0);
            aDst[p] = as0 + kr * 272 + m4 * 16;
        }
    }
    const uint32_t* pB[4];
    uint32_t bDst[4];
    int bCC[4];
#pragma unroll
    for (int p = 0; p < 4; p++) {
        const int ch = tid + p * 256;
        const int r = ch >> 3, c = ch & 7;
        bCC[p] = c * 4;
        pB[p] = BT + (long)(n0 + r) * ldb + c * 4;
        bDst[p] = bs0 + r * 144 + c * 16;
    }

    auto issue = [&](int it, int stage) {
        const int k0 = it * 32;
        const uint32_t aOff = stage * AS_BYTES;
        const uint32_t bOff = stage * BS_BYTES;
#pragma unroll
        for (int p = 0; p < 2; p++) {
            const bool ok = aMok[p] && (k0 + aCC[p] < K);
            cpasync16(aDst[p] + aOff, ok ? pA[p] : A, ok ? 16u : 0u);
            pA[p] += aStep;
        }
#pragma unroll
        for (int p = 0; p < 4; p++) {
            const bool ok = (k0 + bCC[p] < K);
            cpasync16(bDst[p] + bOff, ok ? pB[p] : BT, ok ? 16u : 0u);
            pB[p] += 32;
        }
        CP_COMMIT();
    };

    auto compute = [&](int stage) {
        const uint32_t as = as0 + stage * AS_BYTES;
        const uint32_t bs = bs0 + stage * BS_BYTES;
#pragma unroll
        for (int ks = 0; ks < 4; ks++) {
            uint32_t a[2][4], b[4][2];
            if constexpr (!TRANS_A) {
#pragma unroll
                for (int mt = 0; mt < 2; mt++) {
                    const uint32_t addr = as +
                        (m_w + mt * 16 + (lane & 15)) * 144 +
                        ks * 32 + ((lane >> 4) << 4);
                    ldsm_x4(a[mt], addr);
                }
            } else {
                const uint32_t base = as + (ks * 8 + t) * 272 + (m_w + g) * 4;
#pragma unroll
                for (int mt = 0; mt < 2; mt++) {
                    const uint32_t ab = base + mt * 64;
                    a[mt][0] = lds32(ab);
                    a[mt][1] = lds32(ab + 32);
                    a[mt][2] = lds32(ab + 4 * 272);
                    a[mt][3] = lds32(ab + 4 * 272 + 32);
                }
            }
            if constexpr (A_CVT) {
#pragma unroll
                for (int mt = 0; mt < 2; mt++)
#pragma unroll
                    for (int q = 0; q < 4; q++)
                        a[mt][q] = f2tf32(__uint_as_float(a[mt][q]));
            }
#pragma unroll
            for (int np = 0; np < 2; np++) {
                uint32_t r4[4];
                const uint32_t addr = bs +
                    (n_w + np * 16 + ((lane >> 4) << 3) + (lane & 7)) * 144 +
                    ks * 32 + (((lane >> 3) & 1) << 4);
                ldsm_x4(r4, addr);
                b[np * 2][0] = r4[0];
                b[np * 2][1] = r4[1];
                b[np * 2 + 1][0] = r4[2];
                b[np * 2 + 1][1] = r4[3];
            }
#pragma unroll
            for (int mt = 0; mt < 2; mt++)
#pragma unroll
                for (int nt = 0; nt < 4; nt++)
                    mma_tf32(acc[mt][nt], a[mt], b[nt][0], b[nt][1]);
        }
    };

    // ---- 2-stage mainloop ----
    issue(0, 0);
    for (int it = 0; it < niter; it++) {
        if (it + 1 < niter) {
            issue(it + 1, (it + 1) & 1);
        } else {
            CP_COMMIT();   // tail-race fix: keep committed count at it+1
        }
        CP_WAIT1();        // groups <= it complete
        __syncthreads();   // stage (it&1) visible to all warps
        compute(it & 1);
        __syncthreads();   // all warps done before next issue overwrites it
    }

    // ---------------- epilogue ----------------
    const int tg = t * 2;
#pragma unroll
    for (int mt = 0; mt < 2; mt++) {
#pragma unroll
        for (int h = 0; h < 2; h++) {
            const long r = m0 + m_w + mt * 16 + g + h * 8;
            if (r >= M) continue;
            float gt = 0.f;
            if (EPI == 2) gt = gate[r * (long)gld + gidx];
#pragma unroll
            for (int nt = 0; nt < 4; nt++) {
                const int col = n_w + nt * 8 + tg;   // [0,128)
                float v0 = acc[mt][nt][h * 2 + 0];
                float v1 = acc[mt][nt][h * 2 + 1];
                if (EPI == 1) {
                    float2 bb = *(const float2*)(bias + n0 + col);
                    v0 = fmaxf(v0 + bb.x, 0.f);
                    v1 = fmaxf(v1 + bb.y, 0.f);
                } else if (EPI == 2) {
                    float2 bb = *(const float2*)(bias + n0 + col);
                    v0 = gt * (v0 + bb.x);
                    v1 = gt * (v1 + bb.y);
                }
                if constexpr (OUT_TF32) {
                    uint32_t* p = (uint32_t*)Cv + cbase + r * (long)ldc + n0 + col;
                    uint2 o;
                    o.x = f2tf32(v0);
                    o.y = f2tf32(v1);
                    *reinterpret_cast<uint2*>(p) = o;
                } else {
                    float* p = (float*)Cv + cbase + r * (long)ldc + n0 + col;
                    if (EPI == 2 && !init_flag) {
                        float2 o = *(const float2*)p;
                        v0 += o.x; v1 += o.y;
                    }
                    *reinterpret_cast<float2*>(p) = make_float2(v0, v1);
                }
            }
        }
    }
}

// ---------------------------------------------------------------------------
// in fp32 [z][R][C] -> out tf32 [z][C][R]   (C % 32 == 0; R guarded)
__global__ void trans_cvt_kernel(const float* __restrict__ src,
                                 uint32_t* __restrict__ dst,
                                 int R, int C, long sIn, long sOut)
{
    __shared__ float tbuf[32][33];
    const int r0 = blockIdx.x * 32, c0 = blockIdx.y * 32, z = blockIdx.z;
    const int tx = threadIdx.x, ty = threadIdx.y;
    const float* in = src + (long)z * sIn;
#pragma unroll
    for (int i = ty; i < 32; i += 8) {
        const int r = r0 + i;
        tbuf[i][tx] = (r < R) ? in[(long)r * C + c0 + tx] : 0.f;
    }
    __syncthreads();
    uint32_t* outp = dst + (long)z * sOut;
#pragma unroll
    for (int i = ty; i < 32; i += 8) {
        const int r = r0 + tx;
        if (r < R) outp[(long)(c0 + i) * R + r] = f2tf32(tbuf[tx][i]);
    }
}

// out[b,n,0:256] = sum_s part[s][b][n][:]; out[b,n,256:512] = ori[b,n,:]
__global__ void finalize_kernel(const float* __restrict__ part,
                                const float* __restrict__ ori,
                                float* __restrict__ out, int total4)
{
    const int idx = blockIdx.x * blockDim.x + threadIdx.x;
    if (idx >= total4) return;
    const int d4 = idx & 63;
    const int bn = idx >> 6;
    const long stride4 = 4L * 2000 * 64;
    float4 s = ((const float4*)part)[idx];
#pragma unroll
    for (int sp = 1; sp < 4; sp++) {
        float4 v = ((const float4*)part)[idx + sp * stride4];
        s.x += v.x; s.y += v.y; s.z += v.z; s.w += v.w;
    }
    ((float4*)out)[(long)bn * 128 + d4] = s;
    float4 o = ((const float4*)ori)[idx];
    ((float4*)out)[(long)bn * 128 + 64 + d4] = o;
}

// ---------------------------------------------------------------------------
extern "C" void kernel_launch(void* const* d_in, const int* in_sizes, int n_in,
                              void* d_out, int out_size)
{
    const float* ed  = (const float*)d_in[0];   // [4,8000,5]
    const float* H   = (const float*)d_in[1];   // [4,8000,2000]
    const float* ori = (const float*)d_in[2];   // [4,2000,256]
    const float* W1  = (const float*)d_in[3];   // [5,256,128]
    const float* b1  = (const float*)d_in[4];   // [5,128]
    const float* W2  = (const float*)d_in[5];   // [5,128,256]
    const float* b2  = (const float*)d_in[6];   // [5,256]
    float* out = (float*)d_out;                 // [4,2000,512]

    uint32_t *oriT, *W1T, *W2T, *edges, *ht5, *efT;
    float *ef, *part;
    cudaGetSymbolAddress((void**)&oriT, g_oriT);
    cudaGetSymbolAddress((void**)&W1T, g_W1T);
    cudaGetSymbolAddress((void**)&W2T, g_W2T);
    cudaGetSymbolAddress((void**)&edges, g_edges);
    cudaGetSymbolAddress((void**)&ht5, g_ht5);
    cudaGetSymbolAddress((void**)&ef, g_ef);
    cudaGetSymbolAddress((void**)&efT, g_efT);
    cudaGetSymbolAddress((void**)&part, g_part);

    const int SM_NT = 2 * (64 * 144 + 128 * 144);   // 55296
    const int SM_T  = 2 * (32 * 272 + 128 * 144);   // 54272
    cudaFuncSetAttribute(gemm_tf32<0, false, true, true>,
                         cudaFuncAttributeMaxDynamicSharedMemorySize, SM_NT);
    cudaFuncSetAttribute(gemm_tf32<1, false, false, true>,
                         cudaFuncAttributeMaxDynamicSharedMemorySize, SM_NT);
    cudaFuncSetAttribute(gemm_tf32<2, false, false, false>,
                         cudaFuncAttributeMaxDynamicSharedMemorySize, SM_NT);
    cudaFuncSetAttribute(gemm_tf32<0, true, true, false>,
                         cudaFuncAttributeMaxDynamicSharedMemorySize, SM_T);

    // 0) transpose+convert B operands to n-major tf32
    trans_cvt_kernel<<<dim3(63, 8, 4), dim3(32, 8)>>>(
        ori, oriT, 2000, 256, 2000L * 256, 2000L * 256);
    trans_cvt_kernel<<<dim3(8, 4, 5), dim3(32, 8)>>>(
        W1, W1T, 256, 128, 256L * 128, 256L * 128);
    trans_cvt_kernel<<<dim3(4, 8, 5), dim3(32, 8)>>>(
        W2, W2T, 128, 256, 128L * 256, 128L * 256);

    // 1) edges = H @ ori   (A = H fp32 + in-loop cvt; B = oriT; tf32 out)
    gemm_tf32<0, false, true, true><<<dim3(125, 2, 4), 256, SM_NT>>>(
        (const uint32_t*)H, oriT, edges, 8000, 256, 2000,
        8000L * 2000, 256L * 2000, 8000L * 256, 0, 0, 0, 4,
        2000, 2000, 256, nullptr, 0, nullptr, 0, 0, 0);

    // 2a) MLP1 for all 5 types in one launch (z = t)
    gemm_tf32<1, false, false, true><<<dim3(500, 1, 5), 256, SM_NT>>>(
        edges, W1T, ht5, 32000, 128, 256,
        0, 128L * 256, 32000L * 128, 0, 0, 0, 5,
        256, 256, 128, b1, 128, nullptr, 0, 0, 0);

    // 2b) MLP2 per type (sequential: ef accumulation)
    for (int t = 0; t < 5; t++) {
        gemm_tf32<2, false, false, false><<<dim3(500, 2, 1), 256, SM_NT>>>(
            ht5 + (long)t * 32000 * 128, W2T + (long)t * 256 * 128, ef,
            32000, 256, 128,
            0, 0, 0, 0, 0, 0, 1,
            128, 128, 256, b2 + t * 256, 0, ed, t, 5, (t == 0) ? 1 : 0);
    }

    // 3) efT = transpose+convert(ef) per batch: [8000,256] -> [256,8000]
    trans_cvt_kernel<<<dim3(250, 8, 4), dim3(32, 8)>>>(
        ef, efT, 8000, 256, 8000L * 256, 8000L * 256);

    // 4) part[s] = H[ks]^T @ ef[ks]  (split-K x4; A = H fp32 TRANS + cvt)
    gemm_tf32<0, true, true, false><<<dim3(32, 2, 16), 256, SM_T>>>(
        (const uint32_t*)H, efT, part, 2000, 256, 2000,
        8000L * 2000, 256L * 8000, 2000L * 256,
        2000L * 2000, 2000, 4L * 2000 * 256, 4,
        2000, 8000, 256, nullptr, 0, nullptr, 0, 0, 0);

    // 5) out = [reduce(part), ori]
    finalize_kernel<<<(4 * 2000 * 64 + 255) / 256, 256>>>(
        part, ori, out, 4 * 2000 * 64);
}

// round 14
// speedup vs baseline: 1.4872x; 1.0680x over previous
#include <cuda_runtime.h>
#include <cstdint>

// ---------------------------------------------------------------------------
// edge_aggregation (B=4, E=8000, N=2000, D=256, HID=128, T=5)
// tf32 mma.sync.m16n8k8 + cp.async 2-stage pipeline + ldmatrix fragments,
// 3 CTAs/SM. Round 14: MLP2 fused across the 5 edge types into ONE K=640
// GEMM via gate linearity: ef = [gate_t*h_t]_cat @ [W2_t]_cat + sum_t gate_t*b2_t.
//   edges = H @ ori                      GEMM1  M=8000 N=256 K=2000  x4
//   htcat[:,t*128:+128] = relu(edges@W1_t+b1_t)*gate_t    MLP1 (1 launch, z=t)
//   ef    = htcat @ W2cat + sum_t gate_t*b2_t             MLP2 (1 launch, K=640)
//   out[:, :256] = H^T @ ef              GEMM3  M=2000 N=256 K=8000  split-K x4
//   out[:, 256:] = ori
// ---------------------------------------------------------------------------

__device__ uint32_t g_oriT[4 * 256 * 2000];      // [b][d][n] tf32
__device__ uint32_t g_W1T[5 * 128 * 256];        // [t][h][d] tf32
__device__ uint32_t g_W2cat[256 * 640];          // [d][t*128+h] tf32
__device__ uint32_t g_edges[32000 * 256];        // tf32 (GEMM1 out)
__device__ uint32_t g_htcat[32000L * 640];       // tf32 (MLP1 out, gated, concat-K)
__device__ float    g_ef[32000 * 256];           // fp32 (MLP2 out)
__device__ uint32_t g_efT[4 * 256 * 8000];       // [b][d][e] tf32
__device__ float    g_part[4L * 4 * 2000 * 256]; // split-K partials

// ---------------- PTX helpers ----------------
__device__ __forceinline__ uint32_t smem_u32(const void* p) {
    uint32_t a;
    asm("{ .reg .u64 t; cvta.to.shared.u64 t, %1; cvt.u32.u64 %0, t; }"
        : "=r"(a) : "l"(p));
    return a;
}
__device__ __forceinline__ void cpasync16(uint32_t dst, const void* src, uint32_t sz) {
    asm volatile("cp.async.cg.shared.global [%0], [%1], 16, %2;"
                 :: "r"(dst), "l"(src), "r"(sz) : "memory");
}
#define CP_COMMIT() asm volatile("cp.async.commit_group;" ::: "memory")
#define CP_WAIT1()  asm volatile("cp.async.wait_group 1;" ::: "memory")

__device__ __forceinline__ uint32_t lds32(uint32_t a) {
    uint32_t v;
    asm volatile("ld.shared.b32 %0, [%1];" : "=r"(v) : "r"(a));
    return v;
}
__device__ __forceinline__ void ldsm_x4(uint32_t (&r)[4], uint32_t a) {
    asm volatile("ldmatrix.sync.aligned.m8n8.x4.shared.b16 {%0,%1,%2,%3}, [%4];"
                 : "=r"(r[0]), "=r"(r[1]), "=r"(r[2]), "=r"(r[3]) : "r"(a));
}
__device__ __forceinline__ uint32_t f2tf32(float x) {
    uint32_t r;
    asm("cvt.rna.tf32.f32 %0, %1;" : "=r"(r) : "f"(x));
    return r;
}
__device__ __forceinline__ void mma_tf32(float (&c)[4], const uint32_t (&a)[4],
                                         uint32_t b0, uint32_t b1) {
    asm volatile(
        "mma.sync.aligned.m16n8k8.row.col.f32.tf32.tf32.f32 "
        "{%0,%1,%2,%3}, {%4,%5,%6,%7}, {%8,%9}, {%0,%1,%2,%3};"
        : "+f"(c[0]), "+f"(c[1]), "+f"(c[2]), "+f"(c[3])
        : "r"(a[0]), "r"(a[1]), "r"(a[2]), "r"(a[3]), "r"(b0), "r"(b1));
}

// ---------------------------------------------------------------------------
// Tile 64x128, K-chunk 32, 256 threads (8 warps: 2M x 4N, 32x32 per warp).
// 2-stage pipeline, 55KB smem/CTA, __launch_bounds__(256,3) -> 3 CTAs/SM.
// Tail iterations commit an empty cp.async group (round-11 race fix).
// EPI 0: C=acc
// EPI 3: C=relu(acc+bias[z])*gate[r*gld+zb]         (MLP1, OUT_TF32)
// EPI 4: C=acc + sum_t gate[r*5+t]*bias[t*256+col]  (fused MLP2, fp32 out)
// ---------------------------------------------------------------------------
template <int EPI, bool TRANS_A, bool A_CVT, bool OUT_TF32>
__global__ __launch_bounds__(256, 3)
void gemm_tf32(const uint32_t* __restrict__ A, const uint32_t* __restrict__ BT,
               void* __restrict__ Cv, int M, int N, int K,
               long sA, long sB, long sC,
               long aSplit, long bSplit, long cSplit, int nz,
               int lda, int ldb, int ldc,
               const float* __restrict__ bias, long biasZ,
               const float* __restrict__ gate, int gld)
{
    constexpr int AS_BYTES = TRANS_A ? 32 * 272 : 64 * 144;
    constexpr int BS_BYTES = 128 * 144;

    extern __shared__ __align__(16) char dyn[];
    const uint32_t as0 = smem_u32(dyn);
    const uint32_t bs0 = as0 + 2 * AS_BYTES;

    const int tid = threadIdx.x;
    const int warp = tid >> 5, lane = tid & 31;
    const int wm = warp & 1, wn = warp >> 1;        // 2M x 4N
    const int m_w = wm * 32, n_w = wn * 32;
    const int g = lane >> 2, t = lane & 3;

    const int zb = blockIdx.z % nz;
    const int sp = blockIdx.z / nz;
    A  += zb * sA + sp * aSplit;
    BT += zb * sB + sp * bSplit;
    bias += zb * biasZ;
    const long cbase = zb * sC + sp * cSplit;

    const long m0 = (long)blockIdx.x * 64;
    const int  n0 = blockIdx.y * 128;

    const int niter = (K + 31) / 32;

    float acc[2][4][4];
#pragma unroll
    for (int a = 0; a < 2; a++)
#pragma unroll
        for (int b = 0; b < 4; b++)
#pragma unroll
            for (int c = 0; c < 4; c++) acc[a][b][c] = 0.f;

    // ---- persistent loader state (pointer-increment) ----
    const uint32_t* pA[2];
    uint32_t aDst[2];
    int aCC[2];
    bool aMok[2];
    int aStep;
    if constexpr (!TRANS_A) {
        aStep = 32;
#pragma unroll
        for (int p = 0; p < 2; p++) {
            const int ch = tid + p * 256;
            const int row = ch >> 3, c = ch & 7;
            const long gm = m0 + row;
            aMok[p] = (gm < M);
            aCC[p] = c * 4;
            pA[p] = A + (aMok[p] ? gm * (long)lda + c * 4 : 0);
            aDst[p] = as0 + row * 144 + c * 16;
        }
    } else {
        aStep = 32 * lda;
#pragma unroll
        for (int p = 0; p < 2; p++) {
            const int ch = tid + p * 256;
            const int kr = ch >> 4, m4 = ch & 15;
            const long gm = m0 + m4 * 4;
            aMok[p] = (gm < M);
            aCC[p] = kr;
            pA[p] = A + (aMok[p] ? (long)kr * lda + gm : 0);
            aDst[p] = as0 + kr * 272 + m4 * 16;
        }
    }
    const uint32_t* pB[4];
    uint32_t bDst[4];
    int bCC[4];
#pragma unroll
    for (int p = 0; p < 4; p++) {
        const int ch = tid + p * 256;
        const int r = ch >> 3, c = ch & 7;
        bCC[p] = c * 4;
        pB[p] = BT + (long)(n0 + r) * ldb + c * 4;
        bDst[p] = bs0 + r * 144 + c * 16;
    }

    auto issue = [&](int it, int stage) {
        const int k0 = it * 32;
        const uint32_t aOff = stage * AS_BYTES;
        const uint32_t bOff = stage * BS_BYTES;
#pragma unroll
        for (int p = 0; p < 2; p++) {
            const bool ok = aMok[p] && (k0 + aCC[p] < K);
            cpasync16(aDst[p] + aOff, ok ? pA[p] : A, ok ? 16u : 0u);
            pA[p] += aStep;
        }
#pragma unroll
        for (int p = 0; p < 4; p++) {
            const bool ok = (k0 + bCC[p] < K);
            cpasync16(bDst[p] + bOff, ok ? pB[p] : BT, ok ? 16u : 0u);
            pB[p] += 32;
        }
        CP_COMMIT();
    };

    auto compute = [&](int stage) {
        const uint32_t as = as0 + stage * AS_BYTES;
        const uint32_t bs = bs0 + stage * BS_BYTES;
#pragma unroll
        for (int ks = 0; ks < 4; ks++) {
            uint32_t a[2][4], b[4][2];
            if constexpr (!TRANS_A) {
#pragma unroll
                for (int mt = 0; mt < 2; mt++) {
                    const uint32_t addr = as +
                        (m_w + mt * 16 + (lane & 15)) * 144 +
                        ks * 32 + ((lane >> 4) << 4);
                    ldsm_x4(a[mt], addr);
                }
            } else {
                const uint32_t base = as + (ks * 8 + t) * 272 + (m_w + g) * 4;
#pragma unroll
                for (int mt = 0; mt < 2; mt++) {
                    const uint32_t ab = base + mt * 64;
                    a[mt][0] = lds32(ab);
                    a[mt][1] = lds32(ab + 32);
                    a[mt][2] = lds32(ab + 4 * 272);
                    a[mt][3] = lds32(ab + 4 * 272 + 32);
                }
            }
            if constexpr (A_CVT) {
#pragma unroll
                for (int mt = 0; mt < 2; mt++)
#pragma unroll
                    for (int q = 0; q < 4; q++)
                        a[mt][q] = f2tf32(__uint_as_float(a[mt][q]));
            }
#pragma unroll
            for (int np = 0; np < 2; np++) {
                uint32_t r4[4];
                const uint32_t addr = bs +
                    (n_w + np * 16 + ((lane >> 4) << 3) + (lane & 7)) * 144 +
                    ks * 32 + (((lane >> 3) & 1) << 4);
                ldsm_x4(r4, addr);
                b[np * 2][0] = r4[0];
                b[np * 2][1] = r4[1];
                b[np * 2 + 1][0] = r4[2];
                b[np * 2 + 1][1] = r4[3];
            }
#pragma unroll
            for (int mt = 0; mt < 2; mt++)
#pragma unroll
                for (int nt = 0; nt < 4; nt++)
                    mma_tf32(acc[mt][nt], a[mt], b[nt][0], b[nt][1]);
        }
    };

    // ---- 2-stage mainloop ----
    issue(0, 0);
    for (int it = 0; it < niter; it++) {
        if (it + 1 < niter) {
            issue(it + 1, (it + 1) & 1);
        } else {
            CP_COMMIT();   // tail-race fix
        }
        CP_WAIT1();
        __syncthreads();
        compute(it & 1);
        __syncthreads();
    }

    // ---------------- epilogue ----------------
    const int tg = t * 2;
#pragma unroll
    for (int mt = 0; mt < 2; mt++) {
#pragma unroll
        for (int h = 0; h < 2; h++) {
            const long r = m0 + m_w + mt * 16 + g + h * 8;
            if (r >= M) continue;
            float gt = 0.f;
            float g5[5];
            if (EPI == 3) gt = gate[r * (long)gld + zb];
            if (EPI == 4) {
                const float* gr = gate + r * 5;
#pragma unroll
                for (int q = 0; q < 5; q++) g5[q] = gr[q];
            }
#pragma unroll
            for (int nt = 0; nt < 4; nt++) {
                const int col = n_w + nt * 8 + tg;   // [0,128)
                float v0 = acc[mt][nt][h * 2 + 0];
                float v1 = acc[mt][nt][h * 2 + 1];
                if (EPI == 3) {
                    float2 bb = *(const float2*)(bias + n0 + col);
                    v0 = fmaxf(v0 + bb.x, 0.f) * gt;
                    v1 = fmaxf(v1 + bb.y, 0.f) * gt;
                } else if (EPI == 4) {
#pragma unroll
                    for (int q = 0; q < 5; q++) {
                        float2 bb = *(const float2*)(bias + q * 256 + n0 + col);
                        v0 += g5[q] * bb.x;
                        v1 += g5[q] * bb.y;
                    }
                }
                if constexpr (OUT_TF32) {
                    uint32_t* p = (uint32_t*)Cv + cbase + r * (long)ldc + n0 + col;
                    uint2 o;
                    o.x = f2tf32(v0);
                    o.y = f2tf32(v1);
                    *reinterpret_cast<uint2*>(p) = o;
                } else {
                    float* p = (float*)Cv + cbase + r * (long)ldc + n0 + col;
                    *reinterpret_cast<float2*>(p) = make_float2(v0, v1);
                }
            }
        }
    }
}

// ---------------------------------------------------------------------------
// in fp32 [z][R][C] -> out tf32: out[z*sOut + (c)*ldOut + r]   (C%32==0)
__global__ void trans_cvt_kernel(const float* __restrict__ src,
                                 uint32_t* __restrict__ dst,
                                 int R, int C, long sIn, long sOut, int ldOut)
{
    __shared__ float tbuf[32][33];
    const int r0 = blockIdx.x * 32, c0 = blockIdx.y * 32, z = blockIdx.z;
    const int tx = threadIdx.x, ty = threadIdx.y;
    const float* in = src + (long)z * sIn;
#pragma unroll
    for (int i = ty; i < 32; i += 8) {
        const int r = r0 + i;
        tbuf[i][tx] = (r < R) ? in[(long)r * C + c0 + tx] : 0.f;
    }
    __syncthreads();
    uint32_t* outp = dst + (long)z * sOut;
#pragma unroll
    for (int i = ty; i < 32; i += 8) {
        const int r = r0 + tx;
        if (r < R) outp[(long)(c0 + i) * ldOut + r] = f2tf32(tbuf[tx][i]);
    }
}

// out[b,n,0:256] = sum_s part[s][b][n][:]; out[b,n,256:512] = ori[b,n,:]
__global__ void finalize_kernel(const float* __restrict__ part,
                                const float* __restrict__ ori,
                                float* __restrict__ out, int total4)
{
    const int idx = blockIdx.x * blockDim.x + threadIdx.x;
    if (idx >= total4) return;
    const int d4 = idx & 63;
    const int bn = idx >> 6;
    const long stride4 = 4L * 2000 * 64;
    float4 s = ((const float4*)part)[idx];
#pragma unroll
    for (int sp = 1; sp < 4; sp++) {
        float4 v = ((const float4*)part)[idx + sp * stride4];
        s.x += v.x; s.y += v.y; s.z += v.z; s.w += v.w;
    }
    ((float4*)out)[(long)bn * 128 + d4] = s;
    float4 o = ((const float4*)ori)[idx];
    ((float4*)out)[(long)bn * 128 + 64 + d4] = o;
}

// ---------------------------------------------------------------------------
extern "C" void kernel_launch(void* const* d_in, const int* in_sizes, int n_in,
                              void* d_out, int out_size)
{
    const float* ed  = (const float*)d_in[0];   // [4,8000,5]
    const float* H   = (const float*)d_in[1];   // [4,8000,2000]
    const float* ori = (const float*)d_in[2];   // [4,2000,256]
    const float* W1  = (const float*)d_in[3];   // [5,256,128]
    const float* b1  = (const float*)d_in[4];   // [5,128]
    const float* W2  = (const float*)d_in[5];   // [5,128,256]
    const float* b2  = (const float*)d_in[6];   // [5,256]
    float* out = (float*)d_out;                 // [4,2000,512]

    uint32_t *oriT, *W1T, *W2cat, *edges, *htcat, *efT;
    float *ef, *part;
    cudaGetSymbolAddress((void**)&oriT, g_oriT);
    cudaGetSymbolAddress((void**)&W1T, g_W1T);
    cudaGetSymbolAddress((void**)&W2cat, g_W2cat);
    cudaGetSymbolAddress((void**)&edges, g_edges);
    cudaGetSymbolAddress((void**)&htcat, g_htcat);
    cudaGetSymbolAddress((void**)&ef, g_ef);
    cudaGetSymbolAddress((void**)&efT, g_efT);
    cudaGetSymbolAddress((void**)&part, g_part);

    const int SM_NT = 2 * (64 * 144 + 128 * 144);   // 55296
    const int SM_T  = 2 * (32 * 272 + 128 * 144);   // 54272
    cudaFuncSetAttribute(gemm_tf32<0, false, true, true>,
                         cudaFuncAttributeMaxDynamicSharedMemorySize, SM_NT);
    cudaFuncSetAttribute(gemm_tf32<3, false, false, true>,
                         cudaFuncAttributeMaxDynamicSharedMemorySize, SM_NT);
    cudaFuncSetAttribute(gemm_tf32<4, false, false, false>,
                         cudaFuncAttributeMaxDynamicSharedMemorySize, SM_NT);
    cudaFuncSetAttribute(gemm_tf32<0, true, true, false>,
                         cudaFuncAttributeMaxDynamicSharedMemorySize, SM_T);

    // 0) transpose+convert B operands
    trans_cvt_kernel<<<dim3(63, 8, 4), dim3(32, 8)>>>(
        ori, oriT, 2000, 256, 2000L * 256, 2000L * 256, 2000);
    trans_cvt_kernel<<<dim3(8, 4, 5), dim3(32, 8)>>>(
        W1, W1T, 256, 128, 256L * 128, 256L * 128, 256);
    // W2 [t][128 h][256 d] -> W2cat[d][t*128+h]  (ldOut=640, z offset = t*128)
    trans_cvt_kernel<<<dim3(4, 8, 5), dim3(32, 8)>>>(
        W2, W2cat, 128, 256, 128L * 256, 128, 640);

    // 1) edges = H @ ori   (A = H fp32 + in-loop cvt; B = oriT; tf32 out)
    gemm_tf32<0, false, true, true><<<dim3(125, 2, 4), 256, SM_NT>>>(
        (const uint32_t*)H, oriT, edges, 8000, 256, 2000,
        8000L * 2000, 256L * 2000, 8000L * 256, 0, 0, 0, 4,
        2000, 2000, 256, nullptr, 0, nullptr, 0);

    // 2a) MLP1 (z = t): htcat[:, t*128:(t+1)*128] = relu(edges@W1_t+b1_t)*gate_t
    gemm_tf32<3, false, false, true><<<dim3(500, 1, 5), 256, SM_NT>>>(
        edges, W1T, htcat, 32000, 128, 256,
        0, 128L * 256, 128 /* z col offset */, 0, 0, 0, 5,
        256, 256, 640, b1, 128, ed, 5);

    // 2b) fused MLP2: ef = htcat @ W2cat + sum_t gate_t*b2_t   (K=640, 1 launch)
    gemm_tf32<4, false, false, false><<<dim3(500, 2, 1), 256, SM_NT>>>(
        htcat, W2cat, ef, 32000, 256, 640,
        0, 0, 0, 0, 0, 0, 1,
        640, 640, 256, b2, 0, ed, 5);

    // 3) efT = transpose+convert(ef) per batch: [8000,256] -> [256,8000]
    trans_cvt_kernel<<<dim3(250, 8, 4), dim3(32, 8)>>>(
        ef, efT, 8000, 256, 8000L * 256, 256L * 8000, 8000);

    // 4) part[s] = H[ks]^T @ ef[ks]  (split-K x4; A = H fp32 TRANS + cvt)
    gemm_tf32<0, true, true, false><<<dim3(32, 2, 16), 256, SM_T>>>(
        (const uint32_t*)H, efT, part, 2000, 256, 2000,
        8000L * 2000, 256L * 8000, 2000L * 256,
        2000L * 2000, 2000, 4L * 2000 * 256, 4,
        2000, 8000, 256, nullptr, 0, nullptr, 0);

    // 5) out = [reduce(part), ori]
    finalize_kernel<<<(4 * 2000 * 64 + 255) / 256, 256>>>(
        part, ori, out, 4 * 2000 * 64);
}